// round 3
// baseline (speedup 1.0000x reference)
#include <cuda_runtime.h>
#include <cstdint>

#define N_NODES 50000
#define N_EDGES 800000
#define IN_CH   512
#define HID     256

// ---------------- scratch (no allocations allowed) ----------------
__device__ float g_deg [N_NODES];
__device__ float g_dinv[N_NODES];
__device__ float g_h   [(size_t)N_NODES * HID];   // GEMM output of current layer
__device__ float g_agg [(size_t)N_NODES * HID];   // aggregation accumulator
__device__ float g_in  [(size_t)N_NODES * HID];   // relu(agg+b) -> next layer input

// ---------------- degree / norm ----------------
__global__ void deg_init_kernel() {
    int i = blockIdx.x * blockDim.x + threadIdx.x;
    if (i < N_NODES) g_deg[i] = 1.0f;   // self-loop
}

__global__ void deg_count_kernel(const int* __restrict__ dst) {
    int e = blockIdx.x * blockDim.x + threadIdx.x;
    if (e < N_EDGES) atomicAdd(&g_deg[__ldg(&dst[e])], 1.0f);
}

__global__ void dinv_kernel() {
    int i = blockIdx.x * blockDim.x + threadIdx.x;
    if (i < N_NODES) g_dinv[i] = rsqrtf(g_deg[i]);  // deg >= 1 always
}

// ---------------- SGEMM: C[M=50000, N=256] = A[M,K] * B[K,256] ----------------
#define BM 128
#define BN 128
#define BK 16
#define TM 8
#define TN 8

__global__ __launch_bounds__(256) void sgemm_kernel(
    int K,
    const float* __restrict__ A,   // [M, K] row-major
    const float* __restrict__ B,   // [K, HID] row-major
    float* __restrict__ C)         // [M, HID] row-major
{
    __shared__ float As[BK][BM];
    __shared__ float Bs[BK][BN];

    const int tid   = threadIdx.x;
    const int crow0 = blockIdx.x * BM;
    const int ccol0 = blockIdx.y * BN;

    const int trow = (tid / (BN / TN)) * TM;   // 0..120 step 8
    const int tcol = (tid % (BN / TN)) * TN;   // 0..120 step 8

    // A-tile load mapping: 128x16 floats = 512 float4, 2 per thread
    const int aRow = tid >> 2;            // 0..63
    const int aCol = (tid & 3) * 4;       // 0,4,8,12
    // B-tile load mapping: 16x128 floats = 512 float4, 2 per thread
    const int bRow = tid >> 5;            // 0..7
    const int bCol = (tid & 31) * 4;      // 0..124

    float acc[TM][TN];
#pragma unroll
    for (int m = 0; m < TM; m++)
#pragma unroll
        for (int n = 0; n < TN; n++) acc[m][n] = 0.0f;

    float regM[TM], regN[TN];

    for (int k0 = 0; k0 < K; k0 += BK) {
        // Load A tile (transposed into As[k][m]) with M-boundary guard
#pragma unroll
        for (int i = 0; i < 2; i++) {
            int r    = aRow + i * 64;
            int grow = crow0 + r;
            float4 v = make_float4(0.f, 0.f, 0.f, 0.f);
            if (grow < N_NODES)
                v = *reinterpret_cast<const float4*>(A + (size_t)grow * K + k0 + aCol);
            As[aCol + 0][r] = v.x;
            As[aCol + 1][r] = v.y;
            As[aCol + 2][r] = v.z;
            As[aCol + 3][r] = v.w;
        }
        // Load B tile (K is multiple of BK; N=256 multiple of BN)
#pragma unroll
        for (int i = 0; i < 2; i++) {
            int r = bRow + i * 8;
            *reinterpret_cast<float4*>(&Bs[r][bCol]) =
                *reinterpret_cast<const float4*>(B + (size_t)(k0 + r) * HID + ccol0 + bCol);
        }
        __syncthreads();

#pragma unroll
        for (int k = 0; k < BK; k++) {
#pragma unroll
            for (int m = 0; m < TM; m += 4) {
                float4 v = *reinterpret_cast<const float4*>(&As[k][trow + m]);
                regM[m + 0] = v.x; regM[m + 1] = v.y; regM[m + 2] = v.z; regM[m + 3] = v.w;
            }
#pragma unroll
            for (int n = 0; n < TN; n += 4) {
                float4 v = *reinterpret_cast<const float4*>(&Bs[k][tcol + n]);
                regN[n + 0] = v.x; regN[n + 1] = v.y; regN[n + 2] = v.z; regN[n + 3] = v.w;
            }
#pragma unroll
            for (int m = 0; m < TM; m++)
#pragma unroll
                for (int n = 0; n < TN; n++)
                    acc[m][n] = fmaf(regM[m], regN[n], acc[m][n]);
        }
        __syncthreads();
    }

#pragma unroll
    for (int m = 0; m < TM; m++) {
        int grow = crow0 + trow + m;
        if (grow < N_NODES) {
#pragma unroll
            for (int n = 0; n < TN; n += 4) {
                *reinterpret_cast<float4*>(C + (size_t)grow * HID + ccol0 + tcol + n) =
                    make_float4(acc[m][n], acc[m][n + 1], acc[m][n + 2], acc[m][n + 3]);
            }
        }
    }
}

// ---------------- self-loop init: agg = h * dinv^2 ----------------
__global__ void self_init_kernel(const float* __restrict__ h) {
    int idx = blockIdx.x * blockDim.x + threadIdx.x;
    const int total = N_NODES * (HID / 4);
    if (idx < total) {
        int node = idx >> 6;                 // /(HID/4)
        float di = g_dinv[node];
        float w  = di * di;
        float4 v = reinterpret_cast<const float4*>(h)[idx];
        reinterpret_cast<float4*>(g_agg)[idx] =
            make_float4(v.x * w, v.y * w, v.z * w, v.w * w);
    }
}

// ---------------- edge aggregation: agg[dst] += norm * h[src] ----------------
__device__ __forceinline__ void red_add_v4(float* p, float4 v) {
    asm volatile("red.global.add.v4.f32 [%0], {%1, %2, %3, %4};"
                 :: "l"(p), "f"(v.x), "f"(v.y), "f"(v.z), "f"(v.w)
                 : "memory");
}

__global__ void edge_agg_kernel(const int* __restrict__ src,
                                const int* __restrict__ dst,
                                const float* __restrict__ h) {
    int gtid   = blockIdx.x * blockDim.x + threadIdx.x;
    int warp   = gtid >> 5;
    int lane   = threadIdx.x & 31;
    int nwarps = (gridDim.x * blockDim.x) >> 5;

    for (int e = warp; e < N_EDGES; e += nwarps) {
        int s = __ldg(&src[e]);   // uniform within warp -> broadcast
        int d = __ldg(&dst[e]);
        float nrm = __ldg(&g_dinv[s]) * __ldg(&g_dinv[d]);

        const float4* hp = reinterpret_cast<const float4*>(h + (size_t)s * HID);
        float* ap = g_agg + (size_t)d * HID;

        float4 v0 = __ldg(&hp[lane]);
        float4 v1 = __ldg(&hp[lane + 32]);
        v0.x *= nrm; v0.y *= nrm; v0.z *= nrm; v0.w *= nrm;
        v1.x *= nrm; v1.y *= nrm; v1.z *= nrm; v1.w *= nrm;
        red_add_v4(ap + lane * 4, v0);
        red_add_v4(ap + 128 + lane * 4, v1);
    }
}

// ---------------- bias + relu: in = relu(agg + b) ----------------
__global__ void bias_relu_kernel(const float* __restrict__ b,
                                 float* __restrict__ outbuf) {
    int idx = blockIdx.x * blockDim.x + threadIdx.x;
    const int total = N_NODES * (HID / 4);
    if (idx < total) {
        int c = (idx & 63) << 2;
        float4 bb = *reinterpret_cast<const float4*>(b + c);
        float4 v  = reinterpret_cast<const float4*>(g_agg)[idx];
        v.x = fmaxf(v.x + bb.x, 0.f);
        v.y = fmaxf(v.y + bb.y, 0.f);
        v.z = fmaxf(v.z + bb.z, 0.f);
        v.w = fmaxf(v.w + bb.w, 0.f);
        reinterpret_cast<float4*>(outbuf)[idx] = v;
    }
}

// ---------------- readout: out[i] = dot(in[i], Wout) + bout ----------------
__global__ void readout_kernel(const float* __restrict__ Wout,
                               const float* __restrict__ bout,
                               float* __restrict__ out) {
    int gtid = blockIdx.x * blockDim.x + threadIdx.x;
    int node = gtid >> 5;
    int lane = threadIdx.x & 31;
    if (node < N_NODES) {
        const float4* hp = reinterpret_cast<const float4*>(g_in + (size_t)node * HID);
        const float4* wp = reinterpret_cast<const float4*>(Wout);
        float4 a = __ldg(&hp[lane]);
        float4 w = __ldg(&wp[lane]);
        float s = a.x * w.x + a.y * w.y + a.z * w.z + a.w * w.w;
        a = __ldg(&hp[lane + 32]);
        w = __ldg(&wp[lane + 32]);
        s += a.x * w.x + a.y * w.y + a.z * w.z + a.w * w.w;
#pragma unroll
        for (int o = 16; o > 0; o >>= 1) s += __shfl_down_sync(0xffffffffu, s, o);
        if (lane == 0) out[node] = s + __ldg(&bout[0]);
    }
}

// ---------------- host launcher ----------------
extern "C" void kernel_launch(void* const* d_in, const int* in_sizes, int n_in,
                              void* d_out, int out_size) {
    const float* x    = (const float*)d_in[0];
    const int*   ei   = (const int*)d_in[1];   // [2, E]; int64 in reference, delivered as int32
    const float* W0   = (const float*)d_in[2];
    const float* b0   = (const float*)d_in[3];
    const float* W1   = (const float*)d_in[4];
    const float* b1   = (const float*)d_in[5];
    const float* W2   = (const float*)d_in[6];
    const float* b2   = (const float*)d_in[7];
    const float* Wout = (const float*)d_in[8];
    const float* bout = (const float*)d_in[9];
    float*       out  = (float*)d_out;

    const int* src = ei;             // edge_index[0]
    const int* dst = ei + N_EDGES;   // edge_index[1]

    float *p_h, *p_in;
    cudaGetSymbolAddress((void**)&p_h,  g_h);
    cudaGetSymbolAddress((void**)&p_in, g_in);
    (void)in_sizes; (void)n_in; (void)out_size;

    const int T = 256;
    const int nodeBlocks = (N_NODES + T - 1) / T;
    const int edgeBlocks = (N_EDGES + T - 1) / T;
    const int elemBlocks = (N_NODES * (HID / 4) + T - 1) / T;

    dim3 gemmGrid((N_NODES + BM - 1) / BM, HID / BN);

    // norm precompute
    deg_init_kernel<<<nodeBlocks, T>>>();
    deg_count_kernel<<<edgeBlocks, T>>>(dst);
    dinv_kernel<<<nodeBlocks, T>>>();

    // layer 0: K = 512, A = x
    sgemm_kernel<<<gemmGrid, T>>>(IN_CH, x, W0, p_h);
    self_init_kernel<<<elemBlocks, T>>>(p_h);
    edge_agg_kernel<<<2048, T>>>(src, dst, p_h);
    bias_relu_kernel<<<elemBlocks, T>>>(b0, p_in);

    // layer 1: K = 256, A = g_in
    sgemm_kernel<<<gemmGrid, T>>>(HID, p_in, W1, p_h);
    self_init_kernel<<<elemBlocks, T>>>(p_h);
    edge_agg_kernel<<<2048, T>>>(src, dst, p_h);
    bias_relu_kernel<<<elemBlocks, T>>>(b1, p_in);

    // layer 2: K = 256, A = g_in
    sgemm_kernel<<<gemmGrid, T>>>(HID, p_in, W2, p_h);
    self_init_kernel<<<elemBlocks, T>>>(p_h);
    edge_agg_kernel<<<2048, T>>>(src, dst, p_h);
    bias_relu_kernel<<<elemBlocks, T>>>(b2, p_in);

    // readout
    const int roBlocks = ((N_NODES * 32) + T - 1) / T;
    readout_kernel<<<roBlocks, T>>>(Wout, bout, out);
}

// round 4
// speedup vs baseline: 1.5436x; 1.5436x over previous
#include <cuda_runtime.h>
#include <cstdint>

#define N_NODES 50000
#define N_EDGES 800000
#define IN_CH   512
#define HID     256

// ---------------- scratch (no allocations allowed) ----------------
__device__ float g_deg [N_NODES];
__device__ float g_dinv[N_NODES];
__device__ float g_h   [(size_t)N_NODES * HID];   // GEMM output (unused downstream, kept for clarity)
__device__ float g_agg [(size_t)N_NODES * HID];   // aggregation accumulator
__device__ float g_in  [(size_t)N_NODES * HID];   // relu(agg+b) -> next layer input

// ---------------- degree / norm ----------------
__global__ void deg_init_kernel() {
    int i = blockIdx.x * blockDim.x + threadIdx.x;
    if (i < N_NODES) g_deg[i] = 1.0f;   // self-loop
}

__global__ void deg_count_kernel(const int* __restrict__ dst) {
    int e = blockIdx.x * blockDim.x + threadIdx.x;
    if (e < N_EDGES) atomicAdd(&g_deg[__ldg(&dst[e])], 1.0f);
}

__global__ void dinv_kernel() {
    int i = blockIdx.x * blockDim.x + threadIdx.x;
    if (i < N_NODES) g_dinv[i] = rsqrtf(g_deg[i]);  // deg >= 1 always
}

// ---------------- tf32 helpers ----------------
__device__ __forceinline__ uint32_t f2tf32(float f) {
    uint32_t u;
    asm("cvt.rna.tf32.f32 %0, %1;" : "=r"(u) : "f"(f));
    return u;
}

__device__ __forceinline__ void mma_tf32(float* c,
                                         uint32_t a0, uint32_t a1, uint32_t a2, uint32_t a3,
                                         uint32_t b0, uint32_t b1) {
    asm volatile(
        "mma.sync.aligned.m16n8k8.row.col.f32.tf32.tf32.f32 "
        "{%0,%1,%2,%3}, {%4,%5,%6,%7}, {%8,%9}, {%0,%1,%2,%3};"
        : "+f"(c[0]), "+f"(c[1]), "+f"(c[2]), "+f"(c[3])
        : "r"(a0), "r"(a1), "r"(a2), "r"(a3), "r"(b0), "r"(b1));
}

// ---------------- tf32 tensor-core GEMM ----------------
// C[M=50000, N=256] = A[M,K] * B[K,256]
// Block tile 128x128, 8 warps in 2(M) x 4(N), warp tile 64x32, BK=32.
// Epilogue: writes g_h = C and g_agg = C * dinv(row)^2 (fused self-loop init).
#define GBM 128
#define GBN 128
#define GBK 32
#define APAD 4
#define BPAD 8

__global__ __launch_bounds__(256) void gemm_tf32_kernel(
    int K,
    const float* __restrict__ A,    // [M, K] row-major
    const float* __restrict__ B,    // [K, HID] row-major
    float* __restrict__ Ch,         // g_h
    float* __restrict__ Cagg)       // g_agg (scaled)
{
    __shared__ uint32_t As[GBM][GBK + APAD];   // tf32 bits
    __shared__ uint32_t Bs[GBK][GBN + BPAD];   // tf32 bits

    const int tid  = threadIdx.x;
    const int lane = tid & 31;
    const int warp = tid >> 5;
    const int wm   = warp >> 2;          // 0..1  (M dir)
    const int wn   = warp & 3;           // 0..3  (N dir)
    const int g    = lane >> 2;          // 0..7
    const int t    = lane & 3;           // 0..3

    const int crow0 = blockIdx.x * GBM;
    const int ccol0 = blockIdx.y * GBN;

    float acc[4][4][4];                  // [fm][fn][c0..c3]
#pragma unroll
    for (int fm = 0; fm < 4; fm++)
#pragma unroll
        for (int fn = 0; fn < 4; fn++)
#pragma unroll
            for (int q = 0; q < 4; q++) acc[fm][fn][q] = 0.0f;

    for (int k0 = 0; k0 < K; k0 += GBK) {
        // Stage A tile: 128 rows x 32 cols = 1024 float4, fully coalesced
#pragma unroll
        for (int i = 0; i < 4; i++) {
            int idx = tid + i * 256;
            int row = idx >> 3;          // 0..127
            int c4  = idx & 7;           // 0..7
            int grow = crow0 + row;
            float4 v = make_float4(0.f, 0.f, 0.f, 0.f);
            if (grow < N_NODES)
                v = *reinterpret_cast<const float4*>(A + (size_t)grow * K + k0 + c4 * 4);
            As[row][c4 * 4 + 0] = f2tf32(v.x);
            As[row][c4 * 4 + 1] = f2tf32(v.y);
            As[row][c4 * 4 + 2] = f2tf32(v.z);
            As[row][c4 * 4 + 3] = f2tf32(v.w);
        }
        // Stage B tile: 32 rows x 128 cols = 1024 float4, fully coalesced
#pragma unroll
        for (int i = 0; i < 4; i++) {
            int idx = tid + i * 256;
            int row = idx >> 5;          // 0..31
            int c4  = idx & 31;          // 0..31
            float4 v = *reinterpret_cast<const float4*>(
                B + (size_t)(k0 + row) * HID + ccol0 + c4 * 4);
            Bs[row][c4 * 4 + 0] = f2tf32(v.x);
            Bs[row][c4 * 4 + 1] = f2tf32(v.y);
            Bs[row][c4 * 4 + 2] = f2tf32(v.z);
            Bs[row][c4 * 4 + 3] = f2tf32(v.w);
        }
        __syncthreads();

#pragma unroll
        for (int kc = 0; kc < GBK / 8; kc++) {
            const int kk = kc * 8;
            uint32_t a[4][4];            // [fm][a0..a3]
            uint32_t b[4][2];            // [fn][b0,b1]
#pragma unroll
            for (int fm = 0; fm < 4; fm++) {
                int r = wm * 64 + fm * 16 + g;
                a[fm][0] = As[r][kk + t];
                a[fm][1] = As[r + 8][kk + t];
                a[fm][2] = As[r][kk + t + 4];
                a[fm][3] = As[r + 8][kk + t + 4];
            }
#pragma unroll
            for (int fn = 0; fn < 4; fn++) {
                int c = wn * 32 + fn * 8 + g;
                b[fn][0] = Bs[kk + t][c];
                b[fn][1] = Bs[kk + t + 4][c];
            }
#pragma unroll
            for (int fm = 0; fm < 4; fm++)
#pragma unroll
                for (int fn = 0; fn < 4; fn++)
                    mma_tf32(acc[fm][fn],
                             a[fm][0], a[fm][1], a[fm][2], a[fm][3],
                             b[fn][0], b[fn][1]);
        }
        __syncthreads();
    }

    // Epilogue: C rows r and r+8 per fragment; cols ccol0 + wn*32 + fn*8 + 2t {+0,+1}
#pragma unroll
    for (int fm = 0; fm < 4; fm++) {
        int r0 = crow0 + wm * 64 + fm * 16 + g;
        int r1 = r0 + 8;
        float w0 = 0.f, w1 = 0.f;
        if (r0 < N_NODES) { float d = __ldg(&g_dinv[r0]); w0 = d * d; }
        if (r1 < N_NODES) { float d = __ldg(&g_dinv[r1]); w1 = d * d; }
#pragma unroll
        for (int fn = 0; fn < 4; fn++) {
            int c = ccol0 + wn * 32 + fn * 8 + 2 * t;
            if (r0 < N_NODES) {
                float2 v = make_float2(acc[fm][fn][0], acc[fm][fn][1]);
                *reinterpret_cast<float2*>(Ch   + (size_t)r0 * HID + c) = v;
                *reinterpret_cast<float2*>(Cagg + (size_t)r0 * HID + c) =
                    make_float2(v.x * w0, v.y * w0);
            }
            if (r1 < N_NODES) {
                float2 v = make_float2(acc[fm][fn][2], acc[fm][fn][3]);
                *reinterpret_cast<float2*>(Ch   + (size_t)r1 * HID + c) = v;
                *reinterpret_cast<float2*>(Cagg + (size_t)r1 * HID + c) =
                    make_float2(v.x * w1, v.y * w1);
            }
        }
    }
}

// ---------------- edge aggregation: agg[dst] += norm * h[src] ----------------
__device__ __forceinline__ void red_add_v4(float* p, float4 v) {
    asm volatile("red.global.add.v4.f32 [%0], {%1, %2, %3, %4};"
                 :: "l"(p), "f"(v.x), "f"(v.y), "f"(v.z), "f"(v.w)
                 : "memory");
}

__global__ void edge_agg_kernel(const int* __restrict__ src,
                                const int* __restrict__ dst,
                                const float* __restrict__ h) {
    int gtid   = blockIdx.x * blockDim.x + threadIdx.x;
    int warp   = gtid >> 5;
    int lane   = threadIdx.x & 31;
    int nwarps = (gridDim.x * blockDim.x) >> 5;

    for (int e = warp; e < N_EDGES; e += nwarps) {
        int s = __ldg(&src[e]);   // uniform within warp -> broadcast
        int d = __ldg(&dst[e]);
        float nrm = __ldg(&g_dinv[s]) * __ldg(&g_dinv[d]);

        const float4* hp = reinterpret_cast<const float4*>(h + (size_t)s * HID);
        float* ap = g_agg + (size_t)d * HID;

        float4 v0 = __ldg(&hp[lane]);
        float4 v1 = __ldg(&hp[lane + 32]);
        v0.x *= nrm; v0.y *= nrm; v0.z *= nrm; v0.w *= nrm;
        v1.x *= nrm; v1.y *= nrm; v1.z *= nrm; v1.w *= nrm;
        red_add_v4(ap + lane * 4, v0);
        red_add_v4(ap + 128 + lane * 4, v1);
    }
}

// ---------------- bias + relu: in = relu(agg + b) ----------------
__global__ void bias_relu_kernel(const float* __restrict__ b,
                                 float* __restrict__ outbuf) {
    int idx = blockIdx.x * blockDim.x + threadIdx.x;
    const int total = N_NODES * (HID / 4);
    if (idx < total) {
        int c = (idx & 63) << 2;
        float4 bb = *reinterpret_cast<const float4*>(b + c);
        float4 v  = reinterpret_cast<const float4*>(g_agg)[idx];
        v.x = fmaxf(v.x + bb.x, 0.f);
        v.y = fmaxf(v.y + bb.y, 0.f);
        v.z = fmaxf(v.z + bb.z, 0.f);
        v.w = fmaxf(v.w + bb.w, 0.f);
        reinterpret_cast<float4*>(outbuf)[idx] = v;
    }
}

// ---------------- fused final: out[i] = relu(agg[i]+b2) . Wout + bout ----------------
__global__ void final_readout_kernel(const float* __restrict__ b2,
                                     const float* __restrict__ Wout,
                                     const float* __restrict__ bout,
                                     float* __restrict__ out) {
    int gtid = blockIdx.x * blockDim.x + threadIdx.x;
    int node = gtid >> 5;
    int lane = threadIdx.x & 31;
    if (node < N_NODES) {
        const float4* hp = reinterpret_cast<const float4*>(g_agg + (size_t)node * HID);
        const float4* wp = reinterpret_cast<const float4*>(Wout);
        const float4* bp = reinterpret_cast<const float4*>(b2);

        float4 a = __ldg(&hp[lane]);
        float4 bb = __ldg(&bp[lane]);
        float4 w = __ldg(&wp[lane]);
        float s = fmaxf(a.x + bb.x, 0.f) * w.x + fmaxf(a.y + bb.y, 0.f) * w.y +
                  fmaxf(a.z + bb.z, 0.f) * w.z + fmaxf(a.w + bb.w, 0.f) * w.w;
        a  = __ldg(&hp[lane + 32]);
        bb = __ldg(&bp[lane + 32]);
        w  = __ldg(&wp[lane + 32]);
        s += fmaxf(a.x + bb.x, 0.f) * w.x + fmaxf(a.y + bb.y, 0.f) * w.y +
             fmaxf(a.z + bb.z, 0.f) * w.z + fmaxf(a.w + bb.w, 0.f) * w.w;
#pragma unroll
        for (int o = 16; o > 0; o >>= 1) s += __shfl_down_sync(0xffffffffu, s, o);
        if (lane == 0) out[node] = s + __ldg(&bout[0]);
    }
}

// ---------------- host launcher ----------------
extern "C" void kernel_launch(void* const* d_in, const int* in_sizes, int n_in,
                              void* d_out, int out_size) {
    const float* x    = (const float*)d_in[0];
    const int*   ei   = (const int*)d_in[1];   // delivered as int32
    const float* W0   = (const float*)d_in[2];
    const float* b0   = (const float*)d_in[3];
    const float* W1   = (const float*)d_in[4];
    const float* b1   = (const float*)d_in[5];
    const float* W2   = (const float*)d_in[6];
    const float* b2   = (const float*)d_in[7];
    const float* Wout = (const float*)d_in[8];
    const float* bout = (const float*)d_in[9];
    float*       out  = (float*)d_out;

    const int* src = ei;             // edge_index[0]
    const int* dst = ei + N_EDGES;   // edge_index[1]

    float *p_h, *p_agg, *p_in;
    cudaGetSymbolAddress((void**)&p_h,   g_h);
    cudaGetSymbolAddress((void**)&p_agg, g_agg);
    cudaGetSymbolAddress((void**)&p_in,  g_in);
    (void)in_sizes; (void)n_in; (void)out_size;

    const int T = 256;
    const int nodeBlocks = (N_NODES + T - 1) / T;
    const int edgeBlocks = (N_EDGES + T - 1) / T;
    const int elemBlocks = (N_NODES * (HID / 4) + T - 1) / T;

    dim3 gemmGrid((N_NODES + GBM - 1) / GBM, HID / GBN);

    // norm precompute
    deg_init_kernel<<<nodeBlocks, T>>>();
    deg_count_kernel<<<edgeBlocks, T>>>(dst);
    dinv_kernel<<<nodeBlocks, T>>>();

    // layer 0: K = 512, A = x   (epilogue seeds g_agg with self-loop term)
    gemm_tf32_kernel<<<gemmGrid, T>>>(IN_CH, x, W0, p_h, p_agg);
    edge_agg_kernel<<<2048, T>>>(src, dst, p_h);
    bias_relu_kernel<<<elemBlocks, T>>>(b0, p_in);

    // layer 1: K = 256, A = g_in
    gemm_tf32_kernel<<<gemmGrid, T>>>(HID, p_in, W1, p_h, p_agg);
    edge_agg_kernel<<<2048, T>>>(src, dst, p_h);
    bias_relu_kernel<<<elemBlocks, T>>>(b1, p_in);

    // layer 2: K = 256, A = g_in
    gemm_tf32_kernel<<<gemmGrid, T>>>(HID, p_in, W2, p_h, p_agg);
    edge_agg_kernel<<<2048, T>>>(src, dst, p_h);

    // fused bias+relu+readout
    const int roBlocks = ((N_NODES * 32) + T - 1) / T;
    final_readout_kernel<<<roBlocks, T>>>(b2, Wout, bout, out);
}

// round 5
// speedup vs baseline: 2.4917x; 1.6142x over previous
#include <cuda_runtime.h>
#include <cstdint>

#define N_NODES 50000
#define N_EDGES 800000
#define IN_CH   512
#define HID     256

// ---------------- scratch (no allocations allowed) ----------------
__device__ int   g_degi  [N_NODES];
__device__ float g_dinv  [N_NODES];
__device__ int   g_rowptr[N_NODES + 1];
__device__ int   g_fill  [N_NODES];
__device__ int   g_esrc  [N_EDGES];
__device__ float g_enorm [N_EDGES];
__device__ float g_h     [(size_t)N_NODES * HID];   // GEMM output of current layer
__device__ float g_in    [(size_t)N_NODES * HID];   // relu(agg+b) -> next layer input

// ---------------- degree / norm / CSR build ----------------
__global__ void zero_kernel() {
    int i = blockIdx.x * blockDim.x + threadIdx.x;
    if (i < N_NODES) { g_degi[i] = 0; g_fill[i] = 0; }
}

__global__ void deg_count_kernel(const int* __restrict__ dst) {
    int e = blockIdx.x * blockDim.x + threadIdx.x;
    if (e < N_EDGES) atomicAdd(&g_degi[__ldg(&dst[e])], 1);
}

__global__ void dinv_kernel() {
    int i = blockIdx.x * blockDim.x + threadIdx.x;
    if (i < N_NODES) g_dinv[i] = rsqrtf((float)(g_degi[i] + 1));  // +1 self-loop
}

// single-block exclusive scan of g_degi -> g_rowptr  (1024 threads, chunk 49)
__global__ void scan_kernel() {
    __shared__ int sums[1024];
    const int CH = (N_NODES + 1023) / 1024;   // 49
    int t = threadIdx.x;
    int b = t * CH;
    int e = min(b + CH, N_NODES);
    int s = 0;
    for (int i = b; i < e; i++) s += g_degi[i];
    sums[t] = s;
    __syncthreads();
    for (int off = 1; off < 1024; off <<= 1) {
        int v = 0;
        if (t >= off) v = sums[t - off];
        __syncthreads();
        sums[t] += v;
        __syncthreads();
    }
    int run = sums[t] - s;    // exclusive prefix
    for (int i = b; i < e; i++) { g_rowptr[i] = run; run += g_degi[i]; }
    if (b < N_NODES && e == N_NODES) g_rowptr[N_NODES] = run;
}

__global__ void scatter_kernel(const int* __restrict__ src,
                               const int* __restrict__ dst) {
    int e = blockIdx.x * blockDim.x + threadIdx.x;
    if (e < N_EDGES) {
        int s = __ldg(&src[e]);
        int d = __ldg(&dst[e]);
        int pos = g_rowptr[d] + atomicAdd(&g_fill[d], 1);
        g_esrc[pos]  = s;
        g_enorm[pos] = g_dinv[s] * g_dinv[d];
    }
}

// ---------------- tf32 helpers ----------------
__device__ __forceinline__ uint32_t f2tf32(float f) {
    uint32_t u;
    asm("cvt.rna.tf32.f32 %0, %1;" : "=r"(u) : "f"(f));
    return u;
}

__device__ __forceinline__ void mma_tf32(float* c,
                                         uint32_t a0, uint32_t a1, uint32_t a2, uint32_t a3,
                                         uint32_t b0, uint32_t b1) {
    asm volatile(
        "mma.sync.aligned.m16n8k8.row.col.f32.tf32.tf32.f32 "
        "{%0,%1,%2,%3}, {%4,%5,%6,%7}, {%8,%9}, {%0,%1,%2,%3};"
        : "+f"(c[0]), "+f"(c[1]), "+f"(c[2]), "+f"(c[3])
        : "r"(a0), "r"(a1), "r"(a2), "r"(a3), "r"(b0), "r"(b1));
}

// ---------------- tf32 tensor-core GEMM: C = A * B ----------------
#define GBM 128
#define GBN 128
#define GBK 32
#define APAD 4
#define BPAD 8

__global__ __launch_bounds__(256) void gemm_tf32_kernel(
    int K,
    const float* __restrict__ A,    // [M, K] row-major
    const float* __restrict__ B,    // [K, HID] row-major
    float* __restrict__ Ch)         // g_h
{
    __shared__ uint32_t As[GBM][GBK + APAD];
    __shared__ uint32_t Bs[GBK][GBN + BPAD];

    const int tid  = threadIdx.x;
    const int lane = tid & 31;
    const int warp = tid >> 5;
    const int wm   = warp >> 2;
    const int wn   = warp & 3;
    const int g    = lane >> 2;
    const int t    = lane & 3;

    const int crow0 = blockIdx.x * GBM;
    const int ccol0 = blockIdx.y * GBN;

    float acc[4][4][4];
#pragma unroll
    for (int fm = 0; fm < 4; fm++)
#pragma unroll
        for (int fn = 0; fn < 4; fn++)
#pragma unroll
            for (int q = 0; q < 4; q++) acc[fm][fn][q] = 0.0f;

    for (int k0 = 0; k0 < K; k0 += GBK) {
#pragma unroll
        for (int i = 0; i < 4; i++) {
            int idx = tid + i * 256;
            int row = idx >> 3;
            int c4  = idx & 7;
            int grow = crow0 + row;
            float4 v = make_float4(0.f, 0.f, 0.f, 0.f);
            if (grow < N_NODES)
                v = *reinterpret_cast<const float4*>(A + (size_t)grow * K + k0 + c4 * 4);
            As[row][c4 * 4 + 0] = f2tf32(v.x);
            As[row][c4 * 4 + 1] = f2tf32(v.y);
            As[row][c4 * 4 + 2] = f2tf32(v.z);
            As[row][c4 * 4 + 3] = f2tf32(v.w);
        }
#pragma unroll
        for (int i = 0; i < 4; i++) {
            int idx = tid + i * 256;
            int row = idx >> 5;
            int c4  = idx & 31;
            float4 v = *reinterpret_cast<const float4*>(
                B + (size_t)(k0 + row) * HID + ccol0 + c4 * 4);
            Bs[row][c4 * 4 + 0] = f2tf32(v.x);
            Bs[row][c4 * 4 + 1] = f2tf32(v.y);
            Bs[row][c4 * 4 + 2] = f2tf32(v.z);
            Bs[row][c4 * 4 + 3] = f2tf32(v.w);
        }
        __syncthreads();

#pragma unroll
        for (int kc = 0; kc < GBK / 8; kc++) {
            const int kk = kc * 8;
            uint32_t a[4][4];
            uint32_t b[4][2];
#pragma unroll
            for (int fm = 0; fm < 4; fm++) {
                int r = wm * 64 + fm * 16 + g;
                a[fm][0] = As[r][kk + t];
                a[fm][1] = As[r + 8][kk + t];
                a[fm][2] = As[r][kk + t + 4];
                a[fm][3] = As[r + 8][kk + t + 4];
            }
#pragma unroll
            for (int fn = 0; fn < 4; fn++) {
                int c = wn * 32 + fn * 8 + g;
                b[fn][0] = Bs[kk + t][c];
                b[fn][1] = Bs[kk + t + 4][c];
            }
#pragma unroll
            for (int fm = 0; fm < 4; fm++)
#pragma unroll
                for (int fn = 0; fn < 4; fn++)
                    mma_tf32(acc[fm][fn],
                             a[fm][0], a[fm][1], a[fm][2], a[fm][3],
                             b[fn][0], b[fn][1]);
        }
        __syncthreads();
    }

#pragma unroll
    for (int fm = 0; fm < 4; fm++) {
        int r0 = crow0 + wm * 64 + fm * 16 + g;
        int r1 = r0 + 8;
#pragma unroll
        for (int fn = 0; fn < 4; fn++) {
            int c = ccol0 + wn * 32 + fn * 8 + 2 * t;
            if (r0 < N_NODES)
                *reinterpret_cast<float2*>(Ch + (size_t)r0 * HID + c) =
                    make_float2(acc[fm][fn][0], acc[fm][fn][1]);
            if (r1 < N_NODES)
                *reinterpret_cast<float2*>(Ch + (size_t)r1 * HID + c) =
                    make_float2(acc[fm][fn][2], acc[fm][fn][3]);
        }
    }
}

// ---------------- CSR aggregation, fused epilogues ----------------
// warp per node; lane owns cols [lane*4, lane*4+4) and [128+lane*4, ...).
// acc = dinv^2 * h[node] + sum_e norm_e * h[src_e];  then epilogue.

__device__ __forceinline__ void agg_node(int node, const float* __restrict__ h,
                                         int lane, float4& a0, float4& a1) {
    a0 = make_float4(0.f, 0.f, 0.f, 0.f);
    a1 = make_float4(0.f, 0.f, 0.f, 0.f);
    int p0 = g_rowptr[node];
    int p1 = g_rowptr[node + 1];
    for (int base = p0; base < p1; base += 32) {
        int nn = min(32, p1 - base);
        int   sv = 0; float nv = 0.f;
        if (base + lane < p1) {
            sv = __ldg(&g_esrc[base + lane]);
            nv = __ldg(&g_enorm[base + lane]);
        }
        for (int j = 0; j < nn; j++) {
            int   s   = __shfl_sync(0xffffffffu, sv, j);
            float nrm = __shfl_sync(0xffffffffu, nv, j);
            const float4* hp = reinterpret_cast<const float4*>(h + (size_t)s * HID);
            float4 v0 = __ldg(&hp[lane]);
            float4 v1 = __ldg(&hp[lane + 32]);
            a0.x = fmaf(nrm, v0.x, a0.x); a0.y = fmaf(nrm, v0.y, a0.y);
            a0.z = fmaf(nrm, v0.z, a0.z); a0.w = fmaf(nrm, v0.w, a0.w);
            a1.x = fmaf(nrm, v1.x, a1.x); a1.y = fmaf(nrm, v1.y, a1.y);
            a1.z = fmaf(nrm, v1.z, a1.z); a1.w = fmaf(nrm, v1.w, a1.w);
        }
    }
    // self-loop
    float d = g_dinv[node];
    float w = d * d;
    const float4* hp = reinterpret_cast<const float4*>(h + (size_t)node * HID);
    float4 v0 = __ldg(&hp[lane]);
    float4 v1 = __ldg(&hp[lane + 32]);
    a0.x = fmaf(w, v0.x, a0.x); a0.y = fmaf(w, v0.y, a0.y);
    a0.z = fmaf(w, v0.z, a0.z); a0.w = fmaf(w, v0.w, a0.w);
    a1.x = fmaf(w, v1.x, a1.x); a1.y = fmaf(w, v1.y, a1.y);
    a1.z = fmaf(w, v1.z, a1.z); a1.w = fmaf(w, v1.w, a1.w);
}

__global__ void agg_relu_kernel(const float* __restrict__ h,
                                const float* __restrict__ b,
                                float* __restrict__ outbuf) {
    int gtid = blockIdx.x * blockDim.x + threadIdx.x;
    int node = gtid >> 5;
    int lane = threadIdx.x & 31;
    if (node >= N_NODES) return;

    float4 a0, a1;
    agg_node(node, h, lane, a0, a1);

    const float4* bp = reinterpret_cast<const float4*>(b);
    float4 b0 = __ldg(&bp[lane]);
    float4 b1 = __ldg(&bp[lane + 32]);
    a0.x = fmaxf(a0.x + b0.x, 0.f); a0.y = fmaxf(a0.y + b0.y, 0.f);
    a0.z = fmaxf(a0.z + b0.z, 0.f); a0.w = fmaxf(a0.w + b0.w, 0.f);
    a1.x = fmaxf(a1.x + b1.x, 0.f); a1.y = fmaxf(a1.y + b1.y, 0.f);
    a1.z = fmaxf(a1.z + b1.z, 0.f); a1.w = fmaxf(a1.w + b1.w, 0.f);

    float4* op = reinterpret_cast<float4*>(outbuf + (size_t)node * HID);
    op[lane]      = a0;
    op[lane + 32] = a1;
}

__global__ void agg_readout_kernel(const float* __restrict__ h,
                                   const float* __restrict__ b,
                                   const float* __restrict__ Wout,
                                   const float* __restrict__ bout,
                                   float* __restrict__ out) {
    int gtid = blockIdx.x * blockDim.x + threadIdx.x;
    int node = gtid >> 5;
    int lane = threadIdx.x & 31;
    if (node >= N_NODES) return;

    float4 a0, a1;
    agg_node(node, h, lane, a0, a1);

    const float4* bp = reinterpret_cast<const float4*>(b);
    const float4* wp = reinterpret_cast<const float4*>(Wout);
    float4 b0 = __ldg(&bp[lane]);
    float4 b1 = __ldg(&bp[lane + 32]);
    float4 w0 = __ldg(&wp[lane]);
    float4 w1 = __ldg(&wp[lane + 32]);

    float s = fmaxf(a0.x + b0.x, 0.f) * w0.x + fmaxf(a0.y + b0.y, 0.f) * w0.y +
              fmaxf(a0.z + b0.z, 0.f) * w0.z + fmaxf(a0.w + b0.w, 0.f) * w0.w +
              fmaxf(a1.x + b1.x, 0.f) * w1.x + fmaxf(a1.y + b1.y, 0.f) * w1.y +
              fmaxf(a1.z + b1.z, 0.f) * w1.z + fmaxf(a1.w + b1.w, 0.f) * w1.w;
#pragma unroll
    for (int o = 16; o > 0; o >>= 1) s += __shfl_down_sync(0xffffffffu, s, o);
    if (lane == 0) out[node] = s + __ldg(&bout[0]);
}

// ---------------- host launcher ----------------
extern "C" void kernel_launch(void* const* d_in, const int* in_sizes, int n_in,
                              void* d_out, int out_size) {
    const float* x    = (const float*)d_in[0];
    const int*   ei   = (const int*)d_in[1];   // delivered as int32
    const float* W0   = (const float*)d_in[2];
    const float* b0   = (const float*)d_in[3];
    const float* W1   = (const float*)d_in[4];
    const float* b1   = (const float*)d_in[5];
    const float* W2   = (const float*)d_in[6];
    const float* b2   = (const float*)d_in[7];
    const float* Wout = (const float*)d_in[8];
    const float* bout = (const float*)d_in[9];
    float*       out  = (float*)d_out;

    const int* src = ei;             // edge_index[0]
    const int* dst = ei + N_EDGES;   // edge_index[1]

    float *p_h, *p_in;
    cudaGetSymbolAddress((void**)&p_h,  g_h);
    cudaGetSymbolAddress((void**)&p_in, g_in);
    (void)in_sizes; (void)n_in; (void)out_size;

    const int T = 256;
    const int nodeBlocks = (N_NODES + T - 1) / T;
    const int edgeBlocks = (N_EDGES + T - 1) / T;
    const int warpBlocks = (N_NODES * 32 + T - 1) / T;

    dim3 gemmGrid((N_NODES + GBM - 1) / GBM, HID / GBN);

    // CSR build (once per call, reused by all 3 layers)
    zero_kernel<<<nodeBlocks, T>>>();
    deg_count_kernel<<<edgeBlocks, T>>>(dst);
    dinv_kernel<<<nodeBlocks, T>>>();
    scan_kernel<<<1, 1024>>>();
    scatter_kernel<<<edgeBlocks, T>>>(src, dst);

    // layer 0: K = 512, A = x
    gemm_tf32_kernel<<<gemmGrid, T>>>(IN_CH, x, W0, p_h);
    agg_relu_kernel<<<warpBlocks, T>>>(p_h, b0, p_in);

    // layer 1: K = 256
    gemm_tf32_kernel<<<gemmGrid, T>>>(HID, p_in, W1, p_h);
    agg_relu_kernel<<<warpBlocks, T>>>(p_h, b1, p_in);

    // layer 2: K = 256, fused aggregation + bias + relu + readout
    gemm_tf32_kernel<<<gemmGrid, T>>>(HID, p_in, W2, p_h);
    agg_readout_kernel<<<warpBlocks, T>>>(p_h, b2, Wout, bout, out);
}

// round 7
// speedup vs baseline: 2.7240x; 1.0932x over previous
#include <cuda_runtime.h>
#include <cstdint>

#define N_NODES 50000
#define N_EDGES 800000
#define IN_CH   512
#define HID     256

// ---------------- scratch (no allocations allowed) ----------------
#define NB_SCAN ((N_NODES + 255) / 256)   // 196

__device__ int      g_degi  [N_NODES];
__device__ float    g_dinv  [N_NODES];
__device__ int      g_rowptr[N_NODES + 1];
__device__ int      g_fill  [N_NODES];
__device__ int      g_bsum  [NB_SCAN];
__device__ int      g_boff  [NB_SCAN];
__device__ int      g_esrc  [N_EDGES];
__device__ float    g_enorm [N_EDGES];
__device__ uint32_t g_xt    [(size_t)N_NODES * IN_CH];   // tf32-rounded x
__device__ uint32_t g_w0t   [IN_CH * HID];               // tf32-rounded W0
__device__ uint32_t g_w1t   [HID * HID];
__device__ uint32_t g_w2t   [HID * HID];
__device__ float    g_h     [(size_t)N_NODES * HID];     // GEMM output of current layer
__device__ float    g_in    [(size_t)N_NODES * HID];     // tf32-rounded relu(agg+b)

// ---------------- tf32 helpers ----------------
__device__ __forceinline__ uint32_t f2tf32(float f) {
    uint32_t u;
    asm("cvt.rna.tf32.f32 %0, %1;" : "=r"(u) : "f"(f));
    return u;
}

// ---------------- degree / norm / CSR build ----------------
__global__ void zero_kernel() {
    int i = blockIdx.x * blockDim.x + threadIdx.x;
    if (i < N_NODES) { g_degi[i] = 0; g_fill[i] = 0; }
}

__global__ void deg_count_kernel(const int* __restrict__ dst) {
    int e = blockIdx.x * blockDim.x + threadIdx.x;
    if (e < N_EDGES) atomicAdd(&g_degi[__ldg(&dst[e])], 1);
}

__global__ void dinv_kernel() {
    int i = blockIdx.x * blockDim.x + threadIdx.x;
    if (i < N_NODES) g_dinv[i] = rsqrtf((float)(g_degi[i] + 1));  // +1 self-loop
}

// parallel exclusive scan of g_degi -> g_rowptr, 3 stages
__global__ void scan_bsum_kernel() {
    __shared__ int sh[256];
    int t = threadIdx.x;
    int i = blockIdx.x * 256 + t;
    sh[t] = (i < N_NODES) ? g_degi[i] : 0;
    __syncthreads();
    for (int off = 128; off > 0; off >>= 1) {
        if (t < off) sh[t] += sh[t + off];
        __syncthreads();
    }
    if (t == 0) g_bsum[blockIdx.x] = sh[0];
}

__global__ void scan_boff_kernel() {
    __shared__ int sh[256];
    int t = threadIdx.x;
    int v = (t < NB_SCAN) ? g_bsum[t] : 0;
    sh[t] = v;
    __syncthreads();
    for (int off = 1; off < 256; off <<= 1) {
        int u = (t >= off) ? sh[t - off] : 0;
        __syncthreads();
        sh[t] += u;
        __syncthreads();
    }
    if (t < NB_SCAN) g_boff[t] = sh[t] - v;
    if (t == 255) g_rowptr[N_NODES] = sh[255];
}

__global__ void scan_apply_kernel() {
    __shared__ int sh[256];
    int t = threadIdx.x;
    int i = blockIdx.x * 256 + t;
    int v = (i < N_NODES) ? g_degi[i] : 0;
    sh[t] = v;
    __syncthreads();
    for (int off = 1; off < 256; off <<= 1) {
        int u = (t >= off) ? sh[t - off] : 0;
        __syncthreads();
        sh[t] += u;
        __syncthreads();
    }
    if (i < N_NODES) g_rowptr[i] = g_boff[blockIdx.x] + sh[t] - v;
}

__global__ void scatter_kernel(const int* __restrict__ src,
                               const int* __restrict__ dst) {
    int e = blockIdx.x * blockDim.x + threadIdx.x;
    if (e < N_EDGES) {
        int s = __ldg(&src[e]);
        int d = __ldg(&dst[e]);
        int pos = g_rowptr[d] + atomicAdd(&g_fill[d], 1);
        g_esrc[pos]  = s;
        g_enorm[pos] = g_dinv[s] * g_dinv[d];
    }
}

// ---------------- tf32 pre-conversion passes ----------------
__global__ void cvt_x_kernel(const float* __restrict__ x) {
    int i = blockIdx.x * blockDim.x + threadIdx.x;
    const int total = N_NODES * (IN_CH / 4);
    if (i < total) {
        float4 v = reinterpret_cast<const float4*>(x)[i];
        uint4 u = make_uint4(f2tf32(v.x), f2tf32(v.y), f2tf32(v.z), f2tf32(v.w));
        reinterpret_cast<uint4*>(g_xt)[i] = u;
    }
}

__global__ void cvt_w_kernel(const float* __restrict__ W0,
                             const float* __restrict__ W1,
                             const float* __restrict__ W2) {
    int i = blockIdx.x * blockDim.x + threadIdx.x;
    if (i < IN_CH * HID) g_w0t[i] = f2tf32(__ldg(&W0[i]));
    if (i < HID * HID) {
        g_w1t[i] = f2tf32(__ldg(&W1[i]));
        g_w2t[i] = f2tf32(__ldg(&W2[i]));
    }
}

// ---------------- tf32 mma ----------------
__device__ __forceinline__ void mma_tf32(float* c,
                                         uint32_t a0, uint32_t a1, uint32_t a2, uint32_t a3,
                                         uint32_t b0, uint32_t b1) {
    asm volatile(
        "mma.sync.aligned.m16n8k8.row.col.f32.tf32.tf32.f32 "
        "{%0,%1,%2,%3}, {%4,%5,%6,%7}, {%8,%9}, {%0,%1,%2,%3};"
        : "+f"(c[0]), "+f"(c[1]), "+f"(c[2]), "+f"(c[3])
        : "r"(a0), "r"(a1), "r"(a2), "r"(a3), "r"(b0), "r"(b1));
}

// ---------------- tf32 tensor-core GEMM, cp.async double-buffered ----------------
// C[M=50000, N=256] = A[M,K] * B[K,256]; A,B hold pre-rounded tf32 bit patterns.
#define GBM 128
#define GBN 128
#define GBK 32
#define AS_STRIDE (GBK + 4)                    // 36 words/row
#define BS_STRIDE (GBN + 8)                    // 136 words/row
#define A_TILE_WORDS (GBM * AS_STRIDE)         // 4608
#define B_TILE_WORDS (GBK * BS_STRIDE)         // 4352
#define BS_OFF (2 * A_TILE_WORDS)
#define GEMM_SMEM_BYTES ((2 * A_TILE_WORDS + 2 * B_TILE_WORDS) * 4)   // 71680

__global__ __launch_bounds__(256) void gemm_tf32_kernel(
    int K,
    const uint32_t* __restrict__ A,    // [M, K] row-major, tf32 bits
    const uint32_t* __restrict__ B,    // [K, HID] row-major, tf32 bits
    float* __restrict__ Ch)
{
    extern __shared__ uint32_t sm[];
    const uint32_t sbase = (uint32_t)__cvta_generic_to_shared(sm);

    const int tid  = threadIdx.x;
    const int lane = tid & 31;
    const int warp = tid >> 5;
    const int wm   = warp >> 2;
    const int wn   = warp & 3;
    const int g    = lane >> 2;
    const int t    = lane & 3;

    const int crow0 = blockIdx.x * GBM;
    const int ccol0 = blockIdx.y * GBN;

    float acc[4][4][4];
#pragma unroll
    for (int fm = 0; fm < 4; fm++)
#pragma unroll
        for (int fn = 0; fn < 4; fn++)
#pragma unroll
            for (int q = 0; q < 4; q++) acc[fm][fn][q] = 0.0f;

    auto stage = [&](int buf, int k0) {
#pragma unroll
        for (int i = 0; i < 4; i++) {
            int idx = tid + i * 256;
            int row = idx >> 3;
            int c4  = idx & 7;
            int grow = crow0 + row;
            uint32_t dst = sbase + (uint32_t)(buf * A_TILE_WORDS + row * AS_STRIDE + c4 * 4) * 4u;
            const uint32_t* src = A + (size_t)(grow < N_NODES ? grow : 0) * K + k0 + c4 * 4;
            int sz = (grow < N_NODES) ? 16 : 0;
            asm volatile("cp.async.ca.shared.global [%0], [%1], 16, %2;"
                         :: "r"(dst), "l"(src), "r"(sz));
        }
#pragma unroll
        for (int i = 0; i < 4; i++) {
            int idx = tid + i * 256;
            int row = idx >> 5;
            int c4  = idx & 31;
            uint32_t dst = sbase + (uint32_t)(BS_OFF + buf * B_TILE_WORDS + row * BS_STRIDE + c4 * 4) * 4u;
            const uint32_t* src = B + (size_t)(k0 + row) * HID + ccol0 + c4 * 4;
            asm volatile("cp.async.ca.shared.global [%0], [%1], 16;"
                         :: "r"(dst), "l"(src));
        }
        asm volatile("cp.async.commit_group;");
    };

    stage(0, 0);
    const int nk = K / GBK;

    for (int ki = 0; ki < nk; ki++) {
        const int buf = ki & 1;
        if (ki + 1 < nk) {
            stage(buf ^ 1, (ki + 1) * GBK);
            asm volatile("cp.async.wait_group 1;");
        } else {
            asm volatile("cp.async.wait_group 0;");
        }
        __syncthreads();

        const uint32_t* Asb = sm + buf * A_TILE_WORDS;
        const uint32_t* Bsb = sm + BS_OFF + buf * B_TILE_WORDS;

#pragma unroll
        for (int kc = 0; kc < GBK / 8; kc++) {
            const int kk = kc * 8;
            uint32_t a[4][4];
            uint32_t b[4][2];
#pragma unroll
            for (int fm = 0; fm < 4; fm++) {
                int r = wm * 64 + fm * 16 + g;
                a[fm][0] = Asb[r * AS_STRIDE + kk + t];
                a[fm][1] = Asb[(r + 8) * AS_STRIDE + kk + t];
                a[fm][2] = Asb[r * AS_STRIDE + kk + t + 4];
                a[fm][3] = Asb[(r + 8) * AS_STRIDE + kk + t + 4];
            }
#pragma unroll
            for (int fn = 0; fn < 4; fn++) {
                int c = wn * 32 + fn * 8 + g;
                b[fn][0] = Bsb[(kk + t) * BS_STRIDE + c];
                b[fn][1] = Bsb[(kk + t + 4) * BS_STRIDE + c];
            }
#pragma unroll
            for (int fm = 0; fm < 4; fm++)
#pragma unroll
                for (int fn = 0; fn < 4; fn++)
                    mma_tf32(acc[fm][fn],
                             a[fm][0], a[fm][1], a[fm][2], a[fm][3],
                             b[fn][0], b[fn][1]);
        }
        __syncthreads();
    }

#pragma unroll
    for (int fm = 0; fm < 4; fm++) {
        int r0 = crow0 + wm * 64 + fm * 16 + g;
        int r1 = r0 + 8;
#pragma unroll
        for (int fn = 0; fn < 4; fn++) {
            int c = ccol0 + wn * 32 + fn * 8 + 2 * t;
            if (r0 < N_NODES)
                *reinterpret_cast<float2*>(Ch + (size_t)r0 * HID + c) =
                    make_float2(acc[fm][fn][0], acc[fm][fn][1]);
            if (r1 < N_NODES)
                *reinterpret_cast<float2*>(Ch + (size_t)r1 * HID + c) =
                    make_float2(acc[fm][fn][2], acc[fm][fn][3]);
        }
    }
}

// ---------------- CSR aggregation, fused epilogues ----------------
__device__ __forceinline__ void agg_node(int node, const float* __restrict__ h,
                                         int lane, float4& a0, float4& a1) {
    a0 = make_float4(0.f, 0.f, 0.f, 0.f);
    a1 = make_float4(0.f, 0.f, 0.f, 0.f);
    int p0 = g_rowptr[node];
    int p1 = g_rowptr[node + 1];
    for (int base = p0; base < p1; base += 32) {
        int nn = min(32, p1 - base);
        int   sv = 0; float nv = 0.f;
        if (base + lane < p1) {
            sv = __ldg(&g_esrc[base + lane]);
            nv = __ldg(&g_enorm[base + lane]);
        }
        for (int j = 0; j < nn; j++) {
            int   s   = __shfl_sync(0xffffffffu, sv, j);
            float nrm = __shfl_sync(0xffffffffu, nv, j);
            const float4* hp = reinterpret_cast<const float4*>(h + (size_t)s * HID);
            float4 v0 = __ldg(&hp[lane]);
            float4 v1 = __ldg(&hp[lane + 32]);
            a0.x = fmaf(nrm, v0.x, a0.x); a0.y = fmaf(nrm, v0.y, a0.y);
            a0.z = fmaf(nrm, v0.z, a0.z); a0.w = fmaf(nrm, v0.w, a0.w);
            a1.x = fmaf(nrm, v1.x, a1.x); a1.y = fmaf(nrm, v1.y, a1.y);
            a1.z = fmaf(nrm, v1.z, a1.z); a1.w = fmaf(nrm, v1.w, a1.w);
        }
    }
    // self-loop
    float d = g_dinv[node];
    float w = d * d;
    const float4* hp = reinterpret_cast<const float4*>(h + (size_t)node * HID);
    float4 v0 = __ldg(&hp[lane]);
    float4 v1 = __ldg(&hp[lane + 32]);
    a0.x = fmaf(w, v0.x, a0.x); a0.y = fmaf(w, v0.y, a0.y);
    a0.z = fmaf(w, v0.z, a0.z); a0.w = fmaf(w, v0.w, a0.w);
    a1.x = fmaf(w, v1.x, a1.x); a1.y = fmaf(w, v1.y, a1.y);
    a1.z = fmaf(w, v1.z, a1.z); a1.w = fmaf(w, v1.w, a1.w);
}

// out = tf32_round(relu(agg + b))   (consumed only by next GEMM)
__global__ void agg_relu_kernel(const float* __restrict__ h,
                                const float* __restrict__ b,
                                float* __restrict__ outbuf) {
    int gtid = blockIdx.x * blockDim.x + threadIdx.x;
    int node = gtid >> 5;
    int lane = threadIdx.x & 31;
    if (node >= N_NODES) return;

    float4 a0, a1;
    agg_node(node, h, lane, a0, a1);

    const float4* bp = reinterpret_cast<const float4*>(b);
    float4 b0 = __ldg(&bp[lane]);
    float4 b1 = __ldg(&bp[lane + 32]);
    uint4 u0, u1;
    u0.x = f2tf32(fmaxf(a0.x + b0.x, 0.f)); u0.y = f2tf32(fmaxf(a0.y + b0.y, 0.f));
    u0.z = f2tf32(fmaxf(a0.z + b0.z, 0.f)); u0.w = f2tf32(fmaxf(a0.w + b0.w, 0.f));
    u1.x = f2tf32(fmaxf(a1.x + b1.x, 0.f)); u1.y = f2tf32(fmaxf(a1.y + b1.y, 0.f));
    u1.z = f2tf32(fmaxf(a1.z + b1.z, 0.f)); u1.w = f2tf32(fmaxf(a1.w + b1.w, 0.f));

    uint4* op = reinterpret_cast<uint4*>(outbuf + (size_t)node * HID);
    op[lane]      = u0;
    op[lane + 32] = u1;
}

__global__ void agg_readout_kernel(const float* __restrict__ h,
                                   const float* __restrict__ b,
                                   const float* __restrict__ Wout,
                                   const float* __restrict__ bout,
                                   float* __restrict__ out) {
    int gtid = blockIdx.x * blockDim.x + threadIdx.x;
    int node = gtid >> 5;
    int lane = threadIdx.x & 31;
    if (node >= N_NODES) return;

    float4 a0, a1;
    agg_node(node, h, lane, a0, a1);

    const float4* bp = reinterpret_cast<const float4*>(b);
    const float4* wp = reinterpret_cast<const float4*>(Wout);
    float4 b0 = __ldg(&bp[lane]);
    float4 b1 = __ldg(&bp[lane + 32]);
    float4 w0 = __ldg(&wp[lane]);
    float4 w1 = __ldg(&wp[lane + 32]);

    float s = fmaxf(a0.x + b0.x, 0.f) * w0.x + fmaxf(a0.y + b0.y, 0.f) * w0.y +
              fmaxf(a0.z + b0.z, 0.f) * w0.z + fmaxf(a0.w + b0.w, 0.f) * w0.w +
              fmaxf(a1.x + b1.x, 0.f) * w1.x + fmaxf(a1.y + b1.y, 0.f) * w1.y +
              fmaxf(a1.z + b1.z, 0.f) * w1.z + fmaxf(a1.w + b1.w, 0.f) * w1.w;
#pragma unroll
    for (int o = 16; o > 0; o >>= 1) s += __shfl_down_sync(0xffffffffu, s, o);
    if (lane == 0) out[node] = s + __ldg(&bout[0]);
}

// ---------------- host launcher ----------------
extern "C" void kernel_launch(void* const* d_in, const int* in_sizes, int n_in,
                              void* d_out, int out_size) {
    const float* x    = (const float*)d_in[0];
    const int*   ei   = (const int*)d_in[1];   // delivered as int32
    const float* W0   = (const float*)d_in[2];
    const float* b0   = (const float*)d_in[3];
    const float* W1   = (const float*)d_in[4];
    const float* b1   = (const float*)d_in[5];
    const float* W2   = (const float*)d_in[6];
    const float* b2   = (const float*)d_in[7];
    const float* Wout = (const float*)d_in[8];
    const float* bout = (const float*)d_in[9];
    float*       out  = (float*)d_out;

    const int* src = ei;             // edge_index[0]
    const int* dst = ei + N_EDGES;   // edge_index[1]

    float *p_h, *p_in;
    uint32_t *p_xt, *p_w0t, *p_w1t, *p_w2t;
    cudaGetSymbolAddress((void**)&p_h,   g_h);
    cudaGetSymbolAddress((void**)&p_in,  g_in);
    cudaGetSymbolAddress((void**)&p_xt,  g_xt);
    cudaGetSymbolAddress((void**)&p_w0t, g_w0t);
    cudaGetSymbolAddress((void**)&p_w1t, g_w1t);
    cudaGetSymbolAddress((void**)&p_w2t, g_w2t);
    (void)in_sizes; (void)n_in; (void)out_size;

    cudaFuncSetAttribute(gemm_tf32_kernel,
                         cudaFuncAttributeMaxDynamicSharedMemorySize, GEMM_SMEM_BYTES);

    const int T = 256;
    const int nodeBlocks = (N_NODES + T - 1) / T;
    const int edgeBlocks = (N_EDGES + T - 1) / T;
    const int warpBlocks = (N_NODES * 32 + T - 1) / T;

    dim3 gemmGrid((N_NODES + GBM - 1) / GBM, HID / GBN);

    // CSR build + tf32 pre-conversion (independent streams of work, same queue)
    zero_kernel<<<nodeBlocks, T>>>();
    deg_count_kernel<<<edgeBlocks, T>>>(dst);
    dinv_kernel<<<nodeBlocks, T>>>();
    scan_bsum_kernel<<<NB_SCAN, 256>>>();
    scan_boff_kernel<<<1, 256>>>();
    scan_apply_kernel<<<NB_SCAN, 256>>>();
    scatter_kernel<<<edgeBlocks, T>>>(src, dst);
    cvt_x_kernel<<<(N_NODES * (IN_CH / 4) + T - 1) / T, T>>>(x);
    cvt_w_kernel<<<(IN_CH * HID + T - 1) / T, T>>>(W0, W1, W2);

    // layer 0: K = 512, A = x(tf32)
    gemm_tf32_kernel<<<gemmGrid, T, GEMM_SMEM_BYTES>>>(IN_CH, p_xt, p_w0t, p_h);
    agg_relu_kernel<<<warpBlocks, T>>>(p_h, b0, p_in);

    // layer 1: K = 256
    gemm_tf32_kernel<<<gemmGrid, T, GEMM_SMEM_BYTES>>>(HID, (const uint32_t*)p_in, p_w1t, p_h);
    agg_relu_kernel<<<warpBlocks, T>>>(p_h, b1, p_in);

    // layer 2: K = 256, fused aggregation + bias + relu + readout
    gemm_tf32_kernel<<<gemmGrid, T, GEMM_SMEM_BYTES>>>(HID, (const uint32_t*)p_in, p_w2t, p_h);
    agg_readout_kernel<<<warpBlocks, T>>>(p_h, b2, Wout, bout, out);
}

// round 8
// speedup vs baseline: 2.8696x; 1.0535x over previous
#include <cuda_runtime.h>
#include <cuda_fp16.h>
#include <cstdint>

#define N_NODES 50000
#define N_EDGES 800000
#define IN_CH   512
#define HID     256

// ---------------- scratch (no allocations allowed) ----------------
#define NB_SCAN ((N_NODES + 255) / 256)   // 196

__device__ int      g_degi  [N_NODES];
__device__ float    g_dinv  [N_NODES];
__device__ int      g_rowptr[N_NODES + 1];
__device__ int      g_fill  [N_NODES];
__device__ int      g_bsum  [NB_SCAN];
__device__ int      g_boff  [NB_SCAN];
__device__ int      g_esrc  [N_EDGES];
__device__ float    g_enorm [N_EDGES];
__device__ uint32_t g_xt    [(size_t)N_NODES * IN_CH];   // tf32-rounded x
__device__ uint32_t g_w0t   [IN_CH * HID];               // tf32-rounded weights
__device__ uint32_t g_w1t   [HID * HID];
__device__ uint32_t g_w2t   [HID * HID];
__device__ __half   g_h     [(size_t)N_NODES * HID];     // GEMM output, fp16 (gather operand)
__device__ float    g_in    [(size_t)N_NODES * HID];     // tf32-rounded relu(agg+b)

// ---------------- tf32 helpers ----------------
__device__ __forceinline__ uint32_t f2tf32(float f) {
    uint32_t u;
    asm("cvt.rna.tf32.f32 %0, %1;" : "=r"(u) : "f"(f));
    return u;
}

// ---------------- degree / norm / CSR build ----------------
__global__ void zero_kernel() {
    int i = blockIdx.x * blockDim.x + threadIdx.x;
    if (i < N_NODES) { g_degi[i] = 0; g_fill[i] = 0; }
}

__global__ void deg_count_kernel(const int* __restrict__ dst) {
    int e = blockIdx.x * blockDim.x + threadIdx.x;
    if (e < N_EDGES) atomicAdd(&g_degi[__ldg(&dst[e])], 1);
}

__global__ void dinv_kernel() {
    int i = blockIdx.x * blockDim.x + threadIdx.x;
    if (i < N_NODES) g_dinv[i] = rsqrtf((float)(g_degi[i] + 1));  // +1 self-loop
}

// parallel exclusive scan of g_degi -> g_rowptr, 3 stages
__global__ void scan_bsum_kernel() {
    __shared__ int sh[256];
    int t = threadIdx.x;
    int i = blockIdx.x * 256 + t;
    sh[t] = (i < N_NODES) ? g_degi[i] : 0;
    __syncthreads();
    for (int off = 128; off > 0; off >>= 1) {
        if (t < off) sh[t] += sh[t + off];
        __syncthreads();
    }
    if (t == 0) g_bsum[blockIdx.x] = sh[0];
}

__global__ void scan_boff_kernel() {
    __shared__ int sh[256];
    int t = threadIdx.x;
    int v = (t < NB_SCAN) ? g_bsum[t] : 0;
    sh[t] = v;
    __syncthreads();
    for (int off = 1; off < 256; off <<= 1) {
        int u = (t >= off) ? sh[t - off] : 0;
        __syncthreads();
        sh[t] += u;
        __syncthreads();
    }
    if (t < NB_SCAN) g_boff[t] = sh[t] - v;
    if (t == 255) g_rowptr[N_NODES] = sh[255];
}

__global__ void scan_apply_kernel() {
    __shared__ int sh[256];
    int t = threadIdx.x;
    int i = blockIdx.x * 256 + t;
    int v = (i < N_NODES) ? g_degi[i] : 0;
    sh[t] = v;
    __syncthreads();
    for (int off = 1; off < 256; off <<= 1) {
        int u = (t >= off) ? sh[t - off] : 0;
        __syncthreads();
        sh[t] += u;
        __syncthreads();
    }
    if (i < N_NODES) g_rowptr[i] = g_boff[blockIdx.x] + sh[t] - v;
}

__global__ void scatter_kernel(const int* __restrict__ src,
                               const int* __restrict__ dst) {
    int e = blockIdx.x * blockDim.x + threadIdx.x;
    if (e < N_EDGES) {
        int s = __ldg(&src[e]);
        int d = __ldg(&dst[e]);
        int pos = g_rowptr[d] + atomicAdd(&g_fill[d], 1);
        g_esrc[pos]  = s;
        g_enorm[pos] = g_dinv[s] * g_dinv[d];
    }
}

// ---------------- tf32 pre-conversion passes ----------------
__global__ void cvt_x_kernel(const float* __restrict__ x) {
    int i = blockIdx.x * blockDim.x + threadIdx.x;
    const int total = N_NODES * (IN_CH / 4);
    if (i < total) {
        float4 v = reinterpret_cast<const float4*>(x)[i];
        uint4 u = make_uint4(f2tf32(v.x), f2tf32(v.y), f2tf32(v.z), f2tf32(v.w));
        reinterpret_cast<uint4*>(g_xt)[i] = u;
    }
}

__global__ void cvt_w_kernel(const float* __restrict__ W0,
                             const float* __restrict__ W1,
                             const float* __restrict__ W2) {
    int i = blockIdx.x * blockDim.x + threadIdx.x;
    if (i < IN_CH * HID) g_w0t[i] = f2tf32(__ldg(&W0[i]));
    if (i < HID * HID) {
        g_w1t[i] = f2tf32(__ldg(&W1[i]));
        g_w2t[i] = f2tf32(__ldg(&W2[i]));
    }
}

// ---------------- tf32 mma ----------------
__device__ __forceinline__ void mma_tf32(float* c,
                                         uint32_t a0, uint32_t a1, uint32_t a2, uint32_t a3,
                                         uint32_t b0, uint32_t b1) {
    asm volatile(
        "mma.sync.aligned.m16n8k8.row.col.f32.tf32.tf32.f32 "
        "{%0,%1,%2,%3}, {%4,%5,%6,%7}, {%8,%9}, {%0,%1,%2,%3};"
        : "+f"(c[0]), "+f"(c[1]), "+f"(c[2]), "+f"(c[3])
        : "r"(a0), "r"(a1), "r"(a2), "r"(a3), "r"(b0), "r"(b1));
}

// ---------------- tf32 tensor-core GEMM, cp.async double-buffered ----------------
// C[M=50000, N=256] = A[M,K] * B[K,256]; A,B hold pre-rounded tf32 bit patterns.
// Epilogue stores C as fp16 (consumed only by the gather-aggregation).
#define GBM 128
#define GBN 128
#define GBK 32
#define AS_STRIDE (GBK + 4)                    // 36 words/row
#define BS_STRIDE (GBN + 8)                    // 136 words/row
#define A_TILE_WORDS (GBM * AS_STRIDE)         // 4608
#define B_TILE_WORDS (GBK * BS_STRIDE)         // 4352
#define BS_OFF (2 * A_TILE_WORDS)
#define GEMM_SMEM_BYTES ((2 * A_TILE_WORDS + 2 * B_TILE_WORDS) * 4)   // 71680

__global__ __launch_bounds__(256) void gemm_tf32_kernel(
    int K,
    const uint32_t* __restrict__ A,    // [M, K] row-major, tf32 bits
    const uint32_t* __restrict__ B,    // [K, HID] row-major, tf32 bits
    __half* __restrict__ Ch)           // [M, HID] fp16
{
    extern __shared__ uint32_t sm[];
    const uint32_t sbase = (uint32_t)__cvta_generic_to_shared(sm);

    const int tid  = threadIdx.x;
    const int lane = tid & 31;
    const int warp = tid >> 5;
    const int wm   = warp >> 2;
    const int wn   = warp & 3;
    const int g    = lane >> 2;
    const int t    = lane & 3;

    const int crow0 = blockIdx.x * GBM;
    const int ccol0 = blockIdx.y * GBN;

    float acc[4][4][4];
#pragma unroll
    for (int fm = 0; fm < 4; fm++)
#pragma unroll
        for (int fn = 0; fn < 4; fn++)
#pragma unroll
            for (int q = 0; q < 4; q++) acc[fm][fn][q] = 0.0f;

    auto stage = [&](int buf, int k0) {
#pragma unroll
        for (int i = 0; i < 4; i++) {
            int idx = tid + i * 256;
            int row = idx >> 3;
            int c4  = idx & 7;
            int grow = crow0 + row;
            uint32_t dst = sbase + (uint32_t)(buf * A_TILE_WORDS + row * AS_STRIDE + c4 * 4) * 4u;
            const uint32_t* src = A + (size_t)(grow < N_NODES ? grow : 0) * K + k0 + c4 * 4;
            int sz = (grow < N_NODES) ? 16 : 0;
            asm volatile("cp.async.ca.shared.global [%0], [%1], 16, %2;"
                         :: "r"(dst), "l"(src), "r"(sz));
        }
#pragma unroll
        for (int i = 0; i < 4; i++) {
            int idx = tid + i * 256;
            int row = idx >> 5;
            int c4  = idx & 31;
            uint32_t dst = sbase + (uint32_t)(BS_OFF + buf * B_TILE_WORDS + row * BS_STRIDE + c4 * 4) * 4u;
            const uint32_t* src = B + (size_t)(k0 + row) * HID + ccol0 + c4 * 4;
            asm volatile("cp.async.ca.shared.global [%0], [%1], 16;"
                         :: "r"(dst), "l"(src));
        }
        asm volatile("cp.async.commit_group;");
    };

    stage(0, 0);
    const int nk = K / GBK;

    for (int ki = 0; ki < nk; ki++) {
        const int buf = ki & 1;
        if (ki + 1 < nk) {
            stage(buf ^ 1, (ki + 1) * GBK);
            asm volatile("cp.async.wait_group 1;");
        } else {
            asm volatile("cp.async.wait_group 0;");
        }
        __syncthreads();

        const uint32_t* Asb = sm + buf * A_TILE_WORDS;
        const uint32_t* Bsb = sm + BS_OFF + buf * B_TILE_WORDS;

#pragma unroll
        for (int kc = 0; kc < GBK / 8; kc++) {
            const int kk = kc * 8;
            uint32_t a[4][4];
            uint32_t b[4][2];
#pragma unroll
            for (int fm = 0; fm < 4; fm++) {
                int r = wm * 64 + fm * 16 + g;
                a[fm][0] = Asb[r * AS_STRIDE + kk + t];
                a[fm][1] = Asb[(r + 8) * AS_STRIDE + kk + t];
                a[fm][2] = Asb[r * AS_STRIDE + kk + t + 4];
                a[fm][3] = Asb[(r + 8) * AS_STRIDE + kk + t + 4];
            }
#pragma unroll
            for (int fn = 0; fn < 4; fn++) {
                int c = wn * 32 + fn * 8 + g;
                b[fn][0] = Bsb[(kk + t) * BS_STRIDE + c];
                b[fn][1] = Bsb[(kk + t + 4) * BS_STRIDE + c];
            }
#pragma unroll
            for (int fm = 0; fm < 4; fm++)
#pragma unroll
                for (int fn = 0; fn < 4; fn++)
                    mma_tf32(acc[fm][fn],
                             a[fm][0], a[fm][1], a[fm][2], a[fm][3],
                             b[fn][0], b[fn][1]);
        }
        __syncthreads();
    }

    // Epilogue: fp16 stores (half2 = 4B aligned, c even)
#pragma unroll
    for (int fm = 0; fm < 4; fm++) {
        int r0 = crow0 + wm * 64 + fm * 16 + g;
        int r1 = r0 + 8;
#pragma unroll
        for (int fn = 0; fn < 4; fn++) {
            int c = ccol0 + wn * 32 + fn * 8 + 2 * t;
            if (r0 < N_NODES)
                *reinterpret_cast<__half2*>(Ch + (size_t)r0 * HID + c) =
                    __float22half2_rn(make_float2(acc[fm][fn][0], acc[fm][fn][1]));
            if (r1 < N_NODES)
                *reinterpret_cast<__half2*>(Ch + (size_t)r1 * HID + c) =
                    __float22half2_rn(make_float2(acc[fm][fn][2], acc[fm][fn][3]));
        }
    }
}

// ---------------- CSR aggregation (fp16 gather), fused epilogues ----------------
// warp per node; lane owns cols [lane*8, lane*8+8).  One uint4 (8 halves) per row gather.
__device__ __forceinline__ void agg_node(int node, const __half* __restrict__ h,
                                         int lane, float acc[8]) {
#pragma unroll
    for (int q = 0; q < 8; q++) acc[q] = 0.0f;

    int p0 = g_rowptr[node];
    int p1 = g_rowptr[node + 1];
    for (int base = p0; base < p1; base += 32) {
        int nn = min(32, p1 - base);
        int   sv = 0; float nv = 0.f;
        if (base + lane < p1) {
            sv = __ldg(&g_esrc[base + lane]);
            nv = __ldg(&g_enorm[base + lane]);
        }
        for (int j = 0; j < nn; j++) {
            int   s   = __shfl_sync(0xffffffffu, sv, j);
            float nrm = __shfl_sync(0xffffffffu, nv, j);
            uint4 raw = __ldg(reinterpret_cast<const uint4*>(h + (size_t)s * HID) + lane);
            const __half2* hv = reinterpret_cast<const __half2*>(&raw);
#pragma unroll
            for (int q = 0; q < 4; q++) {
                float2 f = __half22float2(hv[q]);
                acc[2 * q + 0] = fmaf(nrm, f.x, acc[2 * q + 0]);
                acc[2 * q + 1] = fmaf(nrm, f.y, acc[2 * q + 1]);
            }
        }
    }
    // self-loop
    float d = g_dinv[node];
    float w = d * d;
    uint4 raw = __ldg(reinterpret_cast<const uint4*>(h + (size_t)node * HID) + lane);
    const __half2* hv = reinterpret_cast<const __half2*>(&raw);
#pragma unroll
    for (int q = 0; q < 4; q++) {
        float2 f = __half22float2(hv[q]);
        acc[2 * q + 0] = fmaf(w, f.x, acc[2 * q + 0]);
        acc[2 * q + 1] = fmaf(w, f.y, acc[2 * q + 1]);
    }
}

// out = tf32_round(relu(agg + b))   (consumed only by next GEMM)
__global__ void agg_relu_kernel(const __half* __restrict__ h,
                                const float* __restrict__ b,
                                float* __restrict__ outbuf) {
    int gtid = blockIdx.x * blockDim.x + threadIdx.x;
    int node = gtid >> 5;
    int lane = threadIdx.x & 31;
    if (node >= N_NODES) return;

    float acc[8];
    agg_node(node, h, lane, acc);

    const float4* bp = reinterpret_cast<const float4*>(b);
    float4 b0 = __ldg(&bp[2 * lane]);
    float4 b1 = __ldg(&bp[2 * lane + 1]);
    uint4 u0, u1;
    u0.x = f2tf32(fmaxf(acc[0] + b0.x, 0.f)); u0.y = f2tf32(fmaxf(acc[1] + b0.y, 0.f));
    u0.z = f2tf32(fmaxf(acc[2] + b0.z, 0.f)); u0.w = f2tf32(fmaxf(acc[3] + b0.w, 0.f));
    u1.x = f2tf32(fmaxf(acc[4] + b1.x, 0.f)); u1.y = f2tf32(fmaxf(acc[5] + b1.y, 0.f));
    u1.z = f2tf32(fmaxf(acc[6] + b1.z, 0.f)); u1.w = f2tf32(fmaxf(acc[7] + b1.w, 0.f));

    uint4* op = reinterpret_cast<uint4*>(outbuf + (size_t)node * HID);
    op[2 * lane]     = u0;
    op[2 * lane + 1] = u1;
}

__global__ void agg_readout_kernel(const __half* __restrict__ h,
                                   const float* __restrict__ b,
                                   const float* __restrict__ Wout,
                                   const float* __restrict__ bout,
                                   float* __restrict__ out) {
    int gtid = blockIdx.x * blockDim.x + threadIdx.x;
    int node = gtid >> 5;
    int lane = threadIdx.x & 31;
    if (node >= N_NODES) return;

    float acc[8];
    agg_node(node, h, lane, acc);

    const float4* bp = reinterpret_cast<const float4*>(b);
    const float4* wp = reinterpret_cast<const float4*>(Wout);
    float4 b0 = __ldg(&bp[2 * lane]);
    float4 b1 = __ldg(&bp[2 * lane + 1]);
    float4 w0 = __ldg(&wp[2 * lane]);
    float4 w1 = __ldg(&wp[2 * lane + 1]);

    float s = fmaxf(acc[0] + b0.x, 0.f) * w0.x + fmaxf(acc[1] + b0.y, 0.f) * w0.y +
              fmaxf(acc[2] + b0.z, 0.f) * w0.z + fmaxf(acc[3] + b0.w, 0.f) * w0.w +
              fmaxf(acc[4] + b1.x, 0.f) * w1.x + fmaxf(acc[5] + b1.y, 0.f) * w1.y +
              fmaxf(acc[6] + b1.z, 0.f) * w1.z + fmaxf(acc[7] + b1.w, 0.f) * w1.w;
#pragma unroll
    for (int o = 16; o > 0; o >>= 1) s += __shfl_down_sync(0xffffffffu, s, o);
    if (lane == 0) out[node] = s + __ldg(&bout[0]);
}

// ---------------- host launcher ----------------
extern "C" void kernel_launch(void* const* d_in, const int* in_sizes, int n_in,
                              void* d_out, int out_size) {
    const float* x    = (const float*)d_in[0];
    const int*   ei   = (const int*)d_in[1];   // delivered as int32
    const float* W0   = (const float*)d_in[2];
    const float* b0   = (const float*)d_in[3];
    const float* W1   = (const float*)d_in[4];
    const float* b1   = (const float*)d_in[5];
    const float* W2   = (const float*)d_in[6];
    const float* b2   = (const float*)d_in[7];
    const float* Wout = (const float*)d_in[8];
    const float* bout = (const float*)d_in[9];
    float*       out  = (float*)d_out;

    const int* src = ei;             // edge_index[0]
    const int* dst = ei + N_EDGES;   // edge_index[1]

    __half* p_h;
    float*  p_in;
    uint32_t *p_xt, *p_w0t, *p_w1t, *p_w2t;
    cudaGetSymbolAddress((void**)&p_h,   g_h);
    cudaGetSymbolAddress((void**)&p_in,  g_in);
    cudaGetSymbolAddress((void**)&p_xt,  g_xt);
    cudaGetSymbolAddress((void**)&p_w0t, g_w0t);
    cudaGetSymbolAddress((void**)&p_w1t, g_w1t);
    cudaGetSymbolAddress((void**)&p_w2t, g_w2t);
    (void)in_sizes; (void)n_in; (void)out_size;

    cudaFuncSetAttribute(gemm_tf32_kernel,
                         cudaFuncAttributeMaxDynamicSharedMemorySize, GEMM_SMEM_BYTES);

    const int T = 256;
    const int nodeBlocks = (N_NODES + T - 1) / T;
    const int edgeBlocks = (N_EDGES + T - 1) / T;
    const int warpBlocks = (N_NODES * 32 + T - 1) / T;

    dim3 gemmGrid((N_NODES + GBM - 1) / GBM, HID / GBN);

    // CSR build + tf32 pre-conversion
    zero_kernel<<<nodeBlocks, T>>>();
    deg_count_kernel<<<edgeBlocks, T>>>(dst);
    dinv_kernel<<<nodeBlocks, T>>>();
    scan_bsum_kernel<<<NB_SCAN, 256>>>();
    scan_boff_kernel<<<1, 256>>>();
    scan_apply_kernel<<<NB_SCAN, 256>>>();
    scatter_kernel<<<edgeBlocks, T>>>(src, dst);
    cvt_x_kernel<<<(N_NODES * (IN_CH / 4) + T - 1) / T, T>>>(x);
    cvt_w_kernel<<<(IN_CH * HID + T - 1) / T, T>>>(W0, W1, W2);

    // layer 0: K = 512, A = x(tf32)
    gemm_tf32_kernel<<<gemmGrid, T, GEMM_SMEM_BYTES>>>(IN_CH, p_xt, p_w0t, p_h);
    agg_relu_kernel<<<warpBlocks, T>>>(p_h, b0, p_in);

    // layer 1: K = 256
    gemm_tf32_kernel<<<gemmGrid, T, GEMM_SMEM_BYTES>>>(HID, (const uint32_t*)p_in, p_w1t, p_h);
    agg_relu_kernel<<<warpBlocks, T>>>(p_h, b1, p_in);

    // layer 2: K = 256, fused aggregation + bias + relu + readout
    gemm_tf32_kernel<<<gemmGrid, T, GEMM_SMEM_BYTES>>>(HID, (const uint32_t*)p_in, p_w2t, p_h);
    agg_readout_kernel<<<warpBlocks, T>>>(p_h, b2, Wout, bout, out);
}

// round 9
// speedup vs baseline: 3.6669x; 1.2778x over previous
#include <cuda_runtime.h>
#include <cuda_fp16.h>
#include <cstdint>

#define N_NODES 50000
#define N_EDGES 800000
#define IN_CH   512
#define HID     256

// ---------------- scratch (no allocations allowed) ----------------
#define NB_SCAN ((N_NODES + 255) / 256)   // 196

__device__ int      g_degi  [N_NODES];
__device__ float    g_dinv  [N_NODES];
__device__ int      g_rowptr[N_NODES + 1];
__device__ int      g_fill  [N_NODES];
__device__ int      g_bsum  [NB_SCAN];
__device__ int      g_boff  [NB_SCAN];
__device__ int      g_esrc  [N_EDGES];
__device__ float    g_enorm [N_EDGES];
__device__ __half   g_xh    [(size_t)N_NODES * IN_CH];   // fp16 x
__device__ __half   g_w0h   [IN_CH * HID];               // fp16 W0^T  [n][k]
__device__ __half   g_w1h   [HID * HID];                 // fp16 W1^T
__device__ __half   g_w2h   [HID * HID];                 // fp16 W2^T
__device__ __half   g_h     [(size_t)N_NODES * HID];     // GEMM output (gather operand)
__device__ __half   g_in    [(size_t)N_NODES * HID];     // fp16 relu(agg+b)

// ---------------- degree / norm / CSR build ----------------
__global__ void zero_kernel() {
    int i = blockIdx.x * blockDim.x + threadIdx.x;
    if (i < N_NODES) { g_degi[i] = 0; g_fill[i] = 0; }
}

__global__ void deg_count_kernel(const int* __restrict__ dst) {
    int e = blockIdx.x * blockDim.x + threadIdx.x;
    if (e < N_EDGES) atomicAdd(&g_degi[__ldg(&dst[e])], 1);
}

__global__ void dinv_kernel() {
    int i = blockIdx.x * blockDim.x + threadIdx.x;
    if (i < N_NODES) g_dinv[i] = rsqrtf((float)(g_degi[i] + 1));  // +1 self-loop
}

// parallel exclusive scan of g_degi -> g_rowptr, 3 stages
__global__ void scan_bsum_kernel() {
    __shared__ int sh[256];
    int t = threadIdx.x;
    int i = blockIdx.x * 256 + t;
    sh[t] = (i < N_NODES) ? g_degi[i] : 0;
    __syncthreads();
    for (int off = 128; off > 0; off >>= 1) {
        if (t < off) sh[t] += sh[t + off];
        __syncthreads();
    }
    if (t == 0) g_bsum[blockIdx.x] = sh[0];
}

__global__ void scan_boff_kernel() {
    __shared__ int sh[256];
    int t = threadIdx.x;
    int v = (t < NB_SCAN) ? g_bsum[t] : 0;
    sh[t] = v;
    __syncthreads();
    for (int off = 1; off < 256; off <<= 1) {
        int u = (t >= off) ? sh[t - off] : 0;
        __syncthreads();
        sh[t] += u;
        __syncthreads();
    }
    if (t < NB_SCAN) g_boff[t] = sh[t] - v;
    if (t == 255) g_rowptr[N_NODES] = sh[255];
}

__global__ void scan_apply_kernel() {
    __shared__ int sh[256];
    int t = threadIdx.x;
    int i = blockIdx.x * 256 + t;
    int v = (i < N_NODES) ? g_degi[i] : 0;
    sh[t] = v;
    __syncthreads();
    for (int off = 1; off < 256; off <<= 1) {
        int u = (t >= off) ? sh[t - off] : 0;
        __syncthreads();
        sh[t] += u;
        __syncthreads();
    }
    if (i < N_NODES) g_rowptr[i] = g_boff[blockIdx.x] + sh[t] - v;
}

__global__ void scatter_kernel(const int* __restrict__ src,
                               const int* __restrict__ dst) {
    int e = blockIdx.x * blockDim.x + threadIdx.x;
    if (e < N_EDGES) {
        int s = __ldg(&src[e]);
        int d = __ldg(&dst[e]);
        int pos = g_rowptr[d] + atomicAdd(&g_fill[d], 1);
        g_esrc[pos]  = s;
        g_enorm[pos] = g_dinv[s] * g_dinv[d];
    }
}

// ---------------- fp16 pre-conversion ----------------
__global__ void cvt_x_kernel(const float* __restrict__ x) {
    int i = blockIdx.x * blockDim.x + threadIdx.x;
    const int total = N_NODES * (IN_CH / 4);
    if (i < total) {
        float4 v = reinterpret_cast<const float4*>(x)[i];
        __half2 lo = __floats2half2_rn(v.x, v.y);
        __half2 hi = __floats2half2_rn(v.z, v.w);
        uint2 u;
        u.x = *reinterpret_cast<uint32_t*>(&lo);
        u.y = *reinterpret_cast<uint32_t*>(&hi);
        reinterpret_cast<uint2*>(g_xh)[i] = u;
    }
}

// transpose + fp16: g_wXh[n][k] = W[k][n]
__global__ void cvt_w_kernel(const float* __restrict__ W0,
                             const float* __restrict__ W1,
                             const float* __restrict__ W2) {
    int i = blockIdx.x * blockDim.x + threadIdx.x;
    if (i < IN_CH * HID) {
        int n = i / IN_CH, k = i % IN_CH;
        g_w0h[i] = __float2half(__ldg(&W0[k * HID + n]));
    }
    if (i < HID * HID) {
        int n = i / HID, k = i % HID;
        g_w1h[i] = __float2half(__ldg(&W1[k * HID + n]));
        g_w2h[i] = __float2half(__ldg(&W2[k * HID + n]));
    }
}

// ---------------- fp16 mma m16n8k16 ----------------
__device__ __forceinline__ void mma_f16(float* c,
                                        uint32_t a0, uint32_t a1, uint32_t a2, uint32_t a3,
                                        uint32_t b0, uint32_t b1) {
    asm volatile(
        "mma.sync.aligned.m16n8k16.row.col.f32.f16.f16.f32 "
        "{%0,%1,%2,%3}, {%4,%5,%6,%7}, {%8,%9}, {%0,%1,%2,%3};"
        : "+f"(c[0]), "+f"(c[1]), "+f"(c[2]), "+f"(c[3])
        : "r"(a0), "r"(a1), "r"(a2), "r"(a3), "r"(b0), "r"(b1));
}

// ---------------- fp16 tensor-core GEMM, cp.async double-buffered ----------------
// C[M=50000, N=256] = A[M,K] * W^T[N,K]^T ; A fp16 row-major, Wt fp16 n-major.
#define GBM 128
#define GBN 128
#define GBK 32
#define TILE_STRIDE_H 40                      // halves per row (80 B), conflict-free
#define TILE_BYTES (128 * TILE_STRIDE_H * 2)  // 10240
#define B_BASE (2 * TILE_BYTES)               // byte offset of B buffers
#define GEMM_SMEM_BYTES (4 * TILE_BYTES)      // 40960

__global__ __launch_bounds__(256) void gemm_f16_kernel(
    int K,
    const __half* __restrict__ A,     // [M, K]
    const __half* __restrict__ Wt,    // [N=256, K]  (transposed weights)
    __half* __restrict__ Ch)          // [M, HID]
{
    extern __shared__ char smc[];
    const uint32_t sbase = (uint32_t)__cvta_generic_to_shared(smc);

    const int tid  = threadIdx.x;
    const int lane = tid & 31;
    const int warp = tid >> 5;
    const int wm   = warp >> 2;          // 0..1
    const int wn   = warp & 3;           // 0..3
    const int g    = lane >> 2;          // 0..7
    const int t    = lane & 3;           // 0..3

    const int crow0 = blockIdx.x * GBM;
    const int ccol0 = blockIdx.y * GBN;

    float acc[4][4][4];
#pragma unroll
    for (int fm = 0; fm < 4; fm++)
#pragma unroll
        for (int fn = 0; fn < 4; fn++)
#pragma unroll
            for (int q = 0; q < 4; q++) acc[fm][fn][q] = 0.0f;

    // stage A+B K-tile into buffer buf; rows of 32 halves = 64B = 4x16B chunks
    auto stage = [&](int buf, int k0) {
#pragma unroll
        for (int i = 0; i < 2; i++) {
            int idx   = tid + i * 256;
            int row   = idx >> 2;
            int chunk = idx & 3;
            int grow  = crow0 + row;
            uint32_t dst = sbase + (uint32_t)(buf * TILE_BYTES + row * (TILE_STRIDE_H * 2) + chunk * 16);
            const __half* src = A + (size_t)(grow < N_NODES ? grow : 0) * K + k0 + chunk * 8;
            int sz = (grow < N_NODES) ? 16 : 0;
            asm volatile("cp.async.ca.shared.global [%0], [%1], 16, %2;"
                         :: "r"(dst), "l"(src), "r"(sz));
        }
#pragma unroll
        for (int i = 0; i < 2; i++) {
            int idx   = tid + i * 256;
            int row   = idx >> 2;
            int chunk = idx & 3;
            uint32_t dst = sbase + (uint32_t)(B_BASE + buf * TILE_BYTES + row * (TILE_STRIDE_H * 2) + chunk * 16);
            const __half* src = Wt + (size_t)(ccol0 + row) * K + k0 + chunk * 8;
            asm volatile("cp.async.ca.shared.global [%0], [%1], 16;"
                         :: "r"(dst), "l"(src));
        }
        asm volatile("cp.async.commit_group;");
    };

    stage(0, 0);
    const int nk = K / GBK;

    for (int ki = 0; ki < nk; ki++) {
        const int buf = ki & 1;
        if (ki + 1 < nk) {
            stage(buf ^ 1, (ki + 1) * GBK);
            asm volatile("cp.async.wait_group 1;");
        } else {
            asm volatile("cp.async.wait_group 0;");
        }
        __syncthreads();

        const __half* Asb = reinterpret_cast<const __half*>(smc) + buf * (TILE_BYTES / 2);
        const __half* Bsb = reinterpret_cast<const __half*>(smc) + (B_BASE + buf * TILE_BYTES) / 2;

#pragma unroll
        for (int kc = 0; kc < 2; kc++) {          // two k16 steps per 32-tile
            const int kk = kc * 16;
            uint32_t a[4][4];
            uint32_t b[4][2];
#pragma unroll
            for (int fm = 0; fm < 4; fm++) {
                int r = wm * 64 + fm * 16 + g;
                a[fm][0] = *reinterpret_cast<const uint32_t*>(&Asb[r * TILE_STRIDE_H + kk + 2 * t]);
                a[fm][1] = *reinterpret_cast<const uint32_t*>(&Asb[(r + 8) * TILE_STRIDE_H + kk + 2 * t]);
                a[fm][2] = *reinterpret_cast<const uint32_t*>(&Asb[r * TILE_STRIDE_H + kk + 2 * t + 8]);
                a[fm][3] = *reinterpret_cast<const uint32_t*>(&Asb[(r + 8) * TILE_STRIDE_H + kk + 2 * t + 8]);
            }
#pragma unroll
            for (int fn = 0; fn < 4; fn++) {
                int c = wn * 32 + fn * 8 + g;
                b[fn][0] = *reinterpret_cast<const uint32_t*>(&Bsb[c * TILE_STRIDE_H + kk + 2 * t]);
                b[fn][1] = *reinterpret_cast<const uint32_t*>(&Bsb[c * TILE_STRIDE_H + kk + 2 * t + 8]);
            }
#pragma unroll
            for (int fm = 0; fm < 4; fm++)
#pragma unroll
                for (int fn = 0; fn < 4; fn++)
                    mma_f16(acc[fm][fn],
                            a[fm][0], a[fm][1], a[fm][2], a[fm][3],
                            b[fn][0], b[fn][1]);
        }
        __syncthreads();
    }

    // Epilogue: fp16 stores (half2, c even)
#pragma unroll
    for (int fm = 0; fm < 4; fm++) {
        int r0 = crow0 + wm * 64 + fm * 16 + g;
        int r1 = r0 + 8;
#pragma unroll
        for (int fn = 0; fn < 4; fn++) {
            int c = ccol0 + wn * 32 + fn * 8 + 2 * t;
            if (r0 < N_NODES)
                *reinterpret_cast<__half2*>(Ch + (size_t)r0 * HID + c) =
                    __floats2half2_rn(acc[fm][fn][0], acc[fm][fn][1]);
            if (r1 < N_NODES)
                *reinterpret_cast<__half2*>(Ch + (size_t)r1 * HID + c) =
                    __floats2half2_rn(acc[fm][fn][2], acc[fm][fn][3]);
        }
    }
}

// ---------------- CSR aggregation (fp16 gather), fused epilogues ----------------
// warp per node; lane owns cols [lane*8, lane*8+8).  One uint4 (8 halves) per row gather.
__device__ __forceinline__ void agg_node(int node, const __half* __restrict__ h,
                                         int lane, float acc[8]) {
#pragma unroll
    for (int q = 0; q < 8; q++) acc[q] = 0.0f;

    int p0 = g_rowptr[node];
    int p1 = g_rowptr[node + 1];
    for (int base = p0; base < p1; base += 32) {
        int nn = min(32, p1 - base);
        int   sv = 0; float nv = 0.f;
        if (base + lane < p1) {
            sv = __ldg(&g_esrc[base + lane]);
            nv = __ldg(&g_enorm[base + lane]);
        }
        for (int j = 0; j < nn; j++) {
            int   s   = __shfl_sync(0xffffffffu, sv, j);
            float nrm = __shfl_sync(0xffffffffu, nv, j);
            uint4 raw = __ldg(reinterpret_cast<const uint4*>(h + (size_t)s * HID) + lane);
            const __half2* hv = reinterpret_cast<const __half2*>(&raw);
#pragma unroll
            for (int q = 0; q < 4; q++) {
                float2 f = __half22float2(hv[q]);
                acc[2 * q + 0] = fmaf(nrm, f.x, acc[2 * q + 0]);
                acc[2 * q + 1] = fmaf(nrm, f.y, acc[2 * q + 1]);
            }
        }
    }
    // self-loop
    float d = g_dinv[node];
    float w = d * d;
    uint4 raw = __ldg(reinterpret_cast<const uint4*>(h + (size_t)node * HID) + lane);
    const __half2* hv = reinterpret_cast<const __half2*>(&raw);
#pragma unroll
    for (int q = 0; q < 4; q++) {
        float2 f = __half22float2(hv[q]);
        acc[2 * q + 0] = fmaf(w, f.x, acc[2 * q + 0]);
        acc[2 * q + 1] = fmaf(w, f.y, acc[2 * q + 1]);
    }
}

// out = fp16(relu(agg + b))   (consumed only by next GEMM)
__global__ void agg_relu_kernel(const __half* __restrict__ h,
                                const float* __restrict__ b,
                                __half* __restrict__ outbuf) {
    int gtid = blockIdx.x * blockDim.x + threadIdx.x;
    int node = gtid >> 5;
    int lane = threadIdx.x & 31;
    if (node >= N_NODES) return;

    float acc[8];
    agg_node(node, h, lane, acc);

    const float4* bp = reinterpret_cast<const float4*>(b);
    float4 b0 = __ldg(&bp[2 * lane]);
    float4 b1 = __ldg(&bp[2 * lane + 1]);

    __half2 h0 = __floats2half2_rn(fmaxf(acc[0] + b0.x, 0.f), fmaxf(acc[1] + b0.y, 0.f));
    __half2 h1 = __floats2half2_rn(fmaxf(acc[2] + b0.z, 0.f), fmaxf(acc[3] + b0.w, 0.f));
    __half2 h2 = __floats2half2_rn(fmaxf(acc[4] + b1.x, 0.f), fmaxf(acc[5] + b1.y, 0.f));
    __half2 h3 = __floats2half2_rn(fmaxf(acc[6] + b1.z, 0.f), fmaxf(acc[7] + b1.w, 0.f));

    uint4 u;
    u.x = *reinterpret_cast<uint32_t*>(&h0);
    u.y = *reinterpret_cast<uint32_t*>(&h1);
    u.z = *reinterpret_cast<uint32_t*>(&h2);
    u.w = *reinterpret_cast<uint32_t*>(&h3);
    reinterpret_cast<uint4*>(outbuf + (size_t)node * HID)[lane] = u;
}

__global__ void agg_readout_kernel(const __half* __restrict__ h,
                                   const float* __restrict__ b,
                                   const float* __restrict__ Wout,
                                   const float* __restrict__ bout,
                                   float* __restrict__ out) {
    int gtid = blockIdx.x * blockDim.x + threadIdx.x;
    int node = gtid >> 5;
    int lane = threadIdx.x & 31;
    if (node >= N_NODES) return;

    float acc[8];
    agg_node(node, h, lane, acc);

    const float4* bp = reinterpret_cast<const float4*>(b);
    const float4* wp = reinterpret_cast<const float4*>(Wout);
    float4 b0 = __ldg(&bp[2 * lane]);
    float4 b1 = __ldg(&bp[2 * lane + 1]);
    float4 w0 = __ldg(&wp[2 * lane]);
    float4 w1 = __ldg(&wp[2 * lane + 1]);

    float s = fmaxf(acc[0] + b0.x, 0.f) * w0.x + fmaxf(acc[1] + b0.y, 0.f) * w0.y +
              fmaxf(acc[2] + b0.z, 0.f) * w0.z + fmaxf(acc[3] + b0.w, 0.f) * w0.w +
              fmaxf(acc[4] + b1.x, 0.f) * w1.x + fmaxf(acc[5] + b1.y, 0.f) * w1.y +
              fmaxf(acc[6] + b1.z, 0.f) * w1.z + fmaxf(acc[7] + b1.w, 0.f) * w1.w;
#pragma unroll
    for (int o = 16; o > 0; o >>= 1) s += __shfl_down_sync(0xffffffffu, s, o);
    if (lane == 0) out[node] = s + __ldg(&bout[0]);
}

// ---------------- host launcher ----------------
extern "C" void kernel_launch(void* const* d_in, const int* in_sizes, int n_in,
                              void* d_out, int out_size) {
    const float* x    = (const float*)d_in[0];
    const int*   ei   = (const int*)d_in[1];   // delivered as int32
    const float* W0   = (const float*)d_in[2];
    const float* b0   = (const float*)d_in[3];
    const float* W1   = (const float*)d_in[4];
    const float* b1   = (const float*)d_in[5];
    const float* W2   = (const float*)d_in[6];
    const float* b2   = (const float*)d_in[7];
    const float* Wout = (const float*)d_in[8];
    const float* bout = (const float*)d_in[9];
    float*       out  = (float*)d_out;

    const int* src = ei;             // edge_index[0]
    const int* dst = ei + N_EDGES;   // edge_index[1]

    __half *p_h, *p_in, *p_xh, *p_w0h, *p_w1h, *p_w2h;
    cudaGetSymbolAddress((void**)&p_h,   g_h);
    cudaGetSymbolAddress((void**)&p_in,  g_in);
    cudaGetSymbolAddress((void**)&p_xh,  g_xh);
    cudaGetSymbolAddress((void**)&p_w0h, g_w0h);
    cudaGetSymbolAddress((void**)&p_w1h, g_w1h);
    cudaGetSymbolAddress((void**)&p_w2h, g_w2h);
    (void)in_sizes; (void)n_in; (void)out_size;

    cudaFuncSetAttribute(gemm_f16_kernel,
                         cudaFuncAttributeMaxDynamicSharedMemorySize, GEMM_SMEM_BYTES);

    const int T = 256;
    const int nodeBlocks = (N_NODES + T - 1) / T;
    const int edgeBlocks = (N_EDGES + T - 1) / T;
    const int warpBlocks = (N_NODES * 32 + T - 1) / T;

    dim3 gemmGrid((N_NODES + GBM - 1) / GBM, HID / GBN);

    // CSR build + fp16 pre-conversion
    zero_kernel<<<nodeBlocks, T>>>();
    deg_count_kernel<<<edgeBlocks, T>>>(dst);
    dinv_kernel<<<nodeBlocks, T>>>();
    scan_bsum_kernel<<<NB_SCAN, 256>>>();
    scan_boff_kernel<<<1, 256>>>();
    scan_apply_kernel<<<NB_SCAN, 256>>>();
    scatter_kernel<<<edgeBlocks, T>>>(src, dst);
    cvt_x_kernel<<<(N_NODES * (IN_CH / 4) + T - 1) / T, T>>>(x);
    cvt_w_kernel<<<(IN_CH * HID + T - 1) / T, T>>>(W0, W1, W2);

    // layer 0: K = 512
    gemm_f16_kernel<<<gemmGrid, T, GEMM_SMEM_BYTES>>>(IN_CH, p_xh, p_w0h, p_h);
    agg_relu_kernel<<<warpBlocks, T>>>(p_h, b0, p_in);

    // layer 1: K = 256
    gemm_f16_kernel<<<gemmGrid, T, GEMM_SMEM_BYTES>>>(HID, p_in, p_w1h, p_h);
    agg_relu_kernel<<<warpBlocks, T>>>(p_h, b1, p_in);

    // layer 2: K = 256, fused aggregation + bias + relu + readout
    gemm_f16_kernel<<<gemmGrid, T, GEMM_SMEM_BYTES>>>(HID, p_in, p_w2h, p_h);
    agg_readout_kernel<<<warpBlocks, T>>>(p_h, b2, Wout, bout, out);
}

// round 10
// speedup vs baseline: 4.0718x; 1.1104x over previous
#include <cuda_runtime.h>
#include <cuda_fp16.h>
#include <cstdint>

#define N_NODES 50000
#define N_EDGES 800000
#define IN_CH   512
#define HID     256

// ---------------- scratch (no allocations allowed) ----------------
#define NB_SCAN ((N_NODES + 255) / 256)   // 196

__device__ int      g_degi  [N_NODES];
__device__ float    g_dinv  [N_NODES];
__device__ int      g_rowptr[N_NODES + 1];
__device__ int      g_fill  [N_NODES];
__device__ int      g_bsum  [NB_SCAN];
__device__ int      g_boff  [NB_SCAN];
__device__ int      g_esrc  [N_EDGES];
__device__ float    g_enorm [N_EDGES];
__device__ __half   g_xh    [(size_t)N_NODES * IN_CH];   // fp16 x
__device__ __half   g_w0h   [IN_CH * HID];               // fp16 W0^T  [n][k]
__device__ __half   g_w1h   [HID * HID];                 // fp16 W1^T
__device__ __half   g_w2h   [HID * HID];                 // fp16 W2^T
__device__ __half   g_h     [(size_t)N_NODES * HID];     // GEMM output (gather operand)
__device__ __half   g_in    [(size_t)N_NODES * HID];     // fp16 relu(agg+b)

// ---------------- degree / norm / CSR build ----------------
__global__ void zero_kernel() {
    int i = blockIdx.x * blockDim.x + threadIdx.x;
    if (i < N_NODES) { g_degi[i] = 0; g_fill[i] = 0; }
}

__global__ void deg_count_kernel(const int* __restrict__ dst) {
    int e = blockIdx.x * blockDim.x + threadIdx.x;
    if (e < N_EDGES) atomicAdd(&g_degi[__ldg(&dst[e])], 1);
}

__global__ void dinv_kernel() {
    int i = blockIdx.x * blockDim.x + threadIdx.x;
    if (i < N_NODES) g_dinv[i] = rsqrtf((float)(g_degi[i] + 1));  // +1 self-loop
}

// parallel exclusive scan of g_degi -> g_rowptr, 3 stages
__global__ void scan_bsum_kernel() {
    __shared__ int sh[256];
    int t = threadIdx.x;
    int i = blockIdx.x * 256 + t;
    sh[t] = (i < N_NODES) ? g_degi[i] : 0;
    __syncthreads();
    for (int off = 128; off > 0; off >>= 1) {
        if (t < off) sh[t] += sh[t + off];
        __syncthreads();
    }
    if (t == 0) g_bsum[blockIdx.x] = sh[0];
}

__global__ void scan_boff_kernel() {
    __shared__ int sh[256];
    int t = threadIdx.x;
    int v = (t < NB_SCAN) ? g_bsum[t] : 0;
    sh[t] = v;
    __syncthreads();
    for (int off = 1; off < 256; off <<= 1) {
        int u = (t >= off) ? sh[t - off] : 0;
        __syncthreads();
        sh[t] += u;
        __syncthreads();
    }
    if (t < NB_SCAN) g_boff[t] = sh[t] - v;
    if (t == 255) g_rowptr[N_NODES] = sh[255];
}

__global__ void scan_apply_kernel() {
    __shared__ int sh[256];
    int t = threadIdx.x;
    int i = blockIdx.x * 256 + t;
    int v = (i < N_NODES) ? g_degi[i] : 0;
    sh[t] = v;
    __syncthreads();
    for (int off = 1; off < 256; off <<= 1) {
        int u = (t >= off) ? sh[t - off] : 0;
        __syncthreads();
        sh[t] += u;
        __syncthreads();
    }
    if (i < N_NODES) g_rowptr[i] = g_boff[blockIdx.x] + sh[t] - v;
}

__global__ void scatter_kernel(const int* __restrict__ src,
                               const int* __restrict__ dst) {
    int e = blockIdx.x * blockDim.x + threadIdx.x;
    if (e < N_EDGES) {
        int s = __ldg(&src[e]);
        int d = __ldg(&dst[e]);
        int pos = g_rowptr[d] + atomicAdd(&g_fill[d], 1);
        g_esrc[pos]  = s;
        g_enorm[pos] = g_dinv[s] * g_dinv[d];
    }
}

// ---------------- fp16 pre-conversion ----------------
__global__ void cvt_x_kernel(const float* __restrict__ x) {
    int i = blockIdx.x * blockDim.x + threadIdx.x;
    const int total = N_NODES * (IN_CH / 4);
    if (i < total) {
        float4 v = reinterpret_cast<const float4*>(x)[i];
        __half2 lo = __floats2half2_rn(v.x, v.y);
        __half2 hi = __floats2half2_rn(v.z, v.w);
        uint2 u;
        u.x = *reinterpret_cast<uint32_t*>(&lo);
        u.y = *reinterpret_cast<uint32_t*>(&hi);
        reinterpret_cast<uint2*>(g_xh)[i] = u;
    }
}

// transpose + fp16: g_wXh[n][k] = W[k][n]
__global__ void cvt_w_kernel(const float* __restrict__ W0,
                             const float* __restrict__ W1,
                             const float* __restrict__ W2) {
    int i = blockIdx.x * blockDim.x + threadIdx.x;
    if (i < IN_CH * HID) {
        int n = i / IN_CH, k = i % IN_CH;
        g_w0h[i] = __float2half(__ldg(&W0[k * HID + n]));
    }
    if (i < HID * HID) {
        int n = i / HID, k = i % HID;
        g_w1h[i] = __float2half(__ldg(&W1[k * HID + n]));
        g_w2h[i] = __float2half(__ldg(&W2[k * HID + n]));
    }
}

// ---------------- fp16 mma m16n8k16 + ldmatrix ----------------
__device__ __forceinline__ void mma_f16(float* c,
                                        uint32_t a0, uint32_t a1, uint32_t a2, uint32_t a3,
                                        uint32_t b0, uint32_t b1) {
    asm volatile(
        "mma.sync.aligned.m16n8k16.row.col.f32.f16.f16.f32 "
        "{%0,%1,%2,%3}, {%4,%5,%6,%7}, {%8,%9}, {%0,%1,%2,%3};"
        : "+f"(c[0]), "+f"(c[1]), "+f"(c[2]), "+f"(c[3])
        : "r"(a0), "r"(a1), "r"(a2), "r"(a3), "r"(b0), "r"(b1));
}

__device__ __forceinline__ void ldsm_x4(uint32_t* r, uint32_t addr) {
    asm volatile("ldmatrix.sync.aligned.m8n8.x4.shared.b16 {%0,%1,%2,%3}, [%4];"
                 : "=r"(r[0]), "=r"(r[1]), "=r"(r[2]), "=r"(r[3]) : "r"(addr));
}

// ---------------- fp16 tensor-core GEMM, cp.async 3-stage + ldmatrix ----------------
// C[M=50000, N=256] = A[M,K] * Wt[N,K]^T ; A fp16 row-major, Wt fp16 n-major.
#define GBM 128
#define GBN 128
#define GBK 32
#define TSH 40                                // halves per smem row (80 B), conflict-free
#define TILE_BYTES (128 * TSH * 2)            // 10240
#define B_BASE (3 * TILE_BYTES)
#define GEMM_SMEM_BYTES (6 * TILE_BYTES)      // 61440

__global__ __launch_bounds__(256, 2) void gemm_f16_kernel(
    int K,
    const __half* __restrict__ A,     // [M, K]
    const __half* __restrict__ Wt,    // [N=256, K]
    __half* __restrict__ Ch)          // [M, HID]
{
    extern __shared__ char smc[];
    const uint32_t sbase = (uint32_t)__cvta_generic_to_shared(smc);

    const int tid  = threadIdx.x;
    const int lane = tid & 31;
    const int warp = tid >> 5;
    const int wm   = warp >> 2;          // 0..1
    const int wn   = warp & 3;           // 0..3
    const int g    = lane >> 2;          // 0..7  (epilogue row)
    const int t    = lane & 3;           // 0..3  (epilogue col pair)
    const int lrow = lane & 7;           // ldmatrix row within 8-group
    const int lgrp = lane >> 3;          // ldmatrix group 0..3

    const int crow0 = blockIdx.x * GBM;
    const int ccol0 = blockIdx.y * GBN;

    float acc[4][4][4];
#pragma unroll
    for (int fm = 0; fm < 4; fm++)
#pragma unroll
        for (int fn = 0; fn < 4; fn++)
#pragma unroll
            for (int q = 0; q < 4; q++) acc[fm][fn][q] = 0.0f;

    // ldmatrix byte offsets inside a tile buffer
    // A groups: (r,k),(r+8,k),(r,k+8),(r+8,k+8)
    uint32_t aOff[4];
#pragma unroll
    for (int fm = 0; fm < 4; fm++)
        aOff[fm] = (uint32_t)(((wm * 64 + fm * 16 + ((lgrp & 1) << 3) + lrow) * TSH +
                               ((lgrp >> 1) << 3)) * 2);
    // B groups: (n,k),(n,k+8),(n+8,k),(n+8,k+8) -> regs (fn b0, fn b1, fn+1 b0, fn+1 b1)
    uint32_t bOff[2];
#pragma unroll
    for (int p = 0; p < 2; p++)
        bOff[p] = (uint32_t)(((wn * 32 + p * 16 + ((lgrp >> 1) << 3) + lrow) * TSH +
                              ((lgrp & 1) << 3)) * 2);

    auto stage = [&](int buf, int k0) {
#pragma unroll
        for (int i = 0; i < 2; i++) {
            int idx   = tid + i * 256;
            int row   = idx >> 2;
            int chunk = idx & 3;
            int grow  = crow0 + row;
            uint32_t dstp = sbase + (uint32_t)(buf * TILE_BYTES + row * (TSH * 2) + chunk * 16);
            const __half* srcp = A + (size_t)(grow < N_NODES ? grow : 0) * K + k0 + chunk * 8;
            int sz = (grow < N_NODES) ? 16 : 0;
            asm volatile("cp.async.ca.shared.global [%0], [%1], 16, %2;"
                         :: "r"(dstp), "l"(srcp), "r"(sz));
        }
#pragma unroll
        for (int i = 0; i < 2; i++) {
            int idx   = tid + i * 256;
            int row   = idx >> 2;
            int chunk = idx & 3;
            uint32_t dstp = sbase + (uint32_t)(B_BASE + buf * TILE_BYTES + row * (TSH * 2) + chunk * 16);
            const __half* srcp = Wt + (size_t)(ccol0 + row) * K + k0 + chunk * 8;
            asm volatile("cp.async.ca.shared.global [%0], [%1], 16;"
                         :: "r"(dstp), "l"(srcp));
        }
        asm volatile("cp.async.commit_group;");
    };

    const int nk = K / GBK;        // >= 8 always
    stage(0, 0);
    stage(1, GBK);

    for (int ki = 0; ki < nk; ki++) {
        const int buf = ki % 3;
        if (ki + 1 < nk) {
            asm volatile("cp.async.wait_group 1;");
        } else {
            asm volatile("cp.async.wait_group 0;");
        }
        __syncthreads();
        if (ki + 2 < nk) stage((ki + 2) % 3, (ki + 2) * GBK);

        const uint32_t aBase = sbase + (uint32_t)(buf * TILE_BYTES);
        const uint32_t bBase = sbase + (uint32_t)(B_BASE + buf * TILE_BYTES);

#pragma unroll
        for (int kc = 0; kc < 2; kc++) {
            const uint32_t kb = kc * 32;     // 16 halves = 32 bytes
            uint32_t a[4][4];
            uint32_t b[2][4];
#pragma unroll
            for (int fm = 0; fm < 4; fm++) ldsm_x4(a[fm], aBase + aOff[fm] + kb);
#pragma unroll
            for (int p = 0; p < 2; p++)    ldsm_x4(b[p], bBase + bOff[p] + kb);
#pragma unroll
            for (int fm = 0; fm < 4; fm++)
#pragma unroll
                for (int fn = 0; fn < 4; fn++)
                    mma_f16(acc[fm][fn],
                            a[fm][0], a[fm][1], a[fm][2], a[fm][3],
                            b[fn >> 1][(fn & 1) * 2], b[fn >> 1][(fn & 1) * 2 + 1]);
        }
    }
    __syncthreads();

    // Epilogue: fp16 stores (half2, c even)
#pragma unroll
    for (int fm = 0; fm < 4; fm++) {
        int r0 = crow0 + wm * 64 + fm * 16 + g;
        int r1 = r0 + 8;
#pragma unroll
        for (int fn = 0; fn < 4; fn++) {
            int c = ccol0 + wn * 32 + fn * 8 + 2 * t;
            if (r0 < N_NODES)
                *reinterpret_cast<__half2*>(Ch + (size_t)r0 * HID + c) =
                    __floats2half2_rn(acc[fm][fn][0], acc[fm][fn][1]);
            if (r1 < N_NODES)
                *reinterpret_cast<__half2*>(Ch + (size_t)r1 * HID + c) =
                    __floats2half2_rn(acc[fm][fn][2], acc[fm][fn][3]);
        }
    }
}

// ---------------- CSR aggregation (fp16 gather), fused epilogues ----------------
__device__ __forceinline__ void agg_node(int node, const __half* __restrict__ h,
                                         int lane, float acc[8]) {
#pragma unroll
    for (int q = 0; q < 8; q++) acc[q] = 0.0f;

    int p0 = g_rowptr[node];
    int p1 = g_rowptr[node + 1];
    for (int base = p0; base < p1; base += 32) {
        int nn = min(32, p1 - base);
        int   sv = 0; float nv = 0.f;
        if (base + lane < p1) {
            sv = __ldg(&g_esrc[base + lane]);
            nv = __ldg(&g_enorm[base + lane]);
        }
        for (int j = 0; j < nn; j++) {
            int   s   = __shfl_sync(0xffffffffu, sv, j);
            float nrm = __shfl_sync(0xffffffffu, nv, j);
            uint4 raw = __ldg(reinterpret_cast<const uint4*>(h + (size_t)s * HID) + lane);
            const __half2* hv = reinterpret_cast<const __half2*>(&raw);
#pragma unroll
            for (int q = 0; q < 4; q++) {
                float2 f = __half22float2(hv[q]);
                acc[2 * q + 0] = fmaf(nrm, f.x, acc[2 * q + 0]);
                acc[2 * q + 1] = fmaf(nrm, f.y, acc[2 * q + 1]);
            }
        }
    }
    // self-loop
    float d = g_dinv[node];
    float w = d * d;
    uint4 raw = __ldg(reinterpret_cast<const uint4*>(h + (size_t)node * HID) + lane);
    const __half2* hv = reinterpret_cast<const __half2*>(&raw);
#pragma unroll
    for (int q = 0; q < 4; q++) {
        float2 f = __half22float2(hv[q]);
        acc[2 * q + 0] = fmaf(w, f.x, acc[2 * q + 0]);
        acc[2 * q + 1] = fmaf(w, f.y, acc[2 * q + 1]);
    }
}

__global__ void agg_relu_kernel(const __half* __restrict__ h,
                                const float* __restrict__ b,
                                __half* __restrict__ outbuf) {
    int gtid = blockIdx.x * blockDim.x + threadIdx.x;
    int node = gtid >> 5;
    int lane = threadIdx.x & 31;
    if (node >= N_NODES) return;

    float acc[8];
    agg_node(node, h, lane, acc);

    const float4* bp = reinterpret_cast<const float4*>(b);
    float4 b0 = __ldg(&bp[2 * lane]);
    float4 b1 = __ldg(&bp[2 * lane + 1]);

    __half2 h0 = __floats2half2_rn(fmaxf(acc[0] + b0.x, 0.f), fmaxf(acc[1] + b0.y, 0.f));
    __half2 h1 = __floats2half2_rn(fmaxf(acc[2] + b0.z, 0.f), fmaxf(acc[3] + b0.w, 0.f));
    __half2 h2 = __floats2half2_rn(fmaxf(acc[4] + b1.x, 0.f), fmaxf(acc[5] + b1.y, 0.f));
    __half2 h3 = __floats2half2_rn(fmaxf(acc[6] + b1.z, 0.f), fmaxf(acc[7] + b1.w, 0.f));

    uint4 u;
    u.x = *reinterpret_cast<uint32_t*>(&h0);
    u.y = *reinterpret_cast<uint32_t*>(&h1);
    u.z = *reinterpret_cast<uint32_t*>(&h2);
    u.w = *reinterpret_cast<uint32_t*>(&h3);
    reinterpret_cast<uint4*>(outbuf + (size_t)node * HID)[lane] = u;
}

__global__ void agg_readout_kernel(const __half* __restrict__ h,
                                   const float* __restrict__ b,
                                   const float* __restrict__ Wout,
                                   const float* __restrict__ bout,
                                   float* __restrict__ out) {
    int gtid = blockIdx.x * blockDim.x + threadIdx.x;
    int node = gtid >> 5;
    int lane = threadIdx.x & 31;
    if (node >= N_NODES) return;

    float acc[8];
    agg_node(node, h, lane, acc);

    const float4* bp = reinterpret_cast<const float4*>(b);
    const float4* wp = reinterpret_cast<const float4*>(Wout);
    float4 b0 = __ldg(&bp[2 * lane]);
    float4 b1 = __ldg(&bp[2 * lane + 1]);
    float4 w0 = __ldg(&wp[2 * lane]);
    float4 w1 = __ldg(&wp[2 * lane + 1]);

    float s = fmaxf(acc[0] + b0.x, 0.f) * w0.x + fmaxf(acc[1] + b0.y, 0.f) * w0.y +
              fmaxf(acc[2] + b0.z, 0.f) * w0.z + fmaxf(acc[3] + b0.w, 0.f) * w0.w +
              fmaxf(acc[4] + b1.x, 0.f) * w1.x + fmaxf(acc[5] + b1.y, 0.f) * w1.y +
              fmaxf(acc[6] + b1.z, 0.f) * w1.z + fmaxf(acc[7] + b1.w, 0.f) * w1.w;
#pragma unroll
    for (int o = 16; o > 0; o >>= 1) s += __shfl_down_sync(0xffffffffu, s, o);
    if (lane == 0) out[node] = s + __ldg(&bout[0]);
}

// ---------------- host launcher ----------------
extern "C" void kernel_launch(void* const* d_in, const int* in_sizes, int n_in,
                              void* d_out, int out_size) {
    const float* x    = (const float*)d_in[0];
    const int*   ei   = (const int*)d_in[1];   // delivered as int32
    const float* W0   = (const float*)d_in[2];
    const float* b0   = (const float*)d_in[3];
    const float* W1   = (const float*)d_in[4];
    const float* b1   = (const float*)d_in[5];
    const float* W2   = (const float*)d_in[6];
    const float* b2   = (const float*)d_in[7];
    const float* Wout = (const float*)d_in[8];
    const float* bout = (const float*)d_in[9];
    float*       out  = (float*)d_out;

    const int* src = ei;             // edge_index[0]
    const int* dst = ei + N_EDGES;   // edge_index[1]

    __half *p_h, *p_in, *p_xh, *p_w0h, *p_w1h, *p_w2h;
    cudaGetSymbolAddress((void**)&p_h,   g_h);
    cudaGetSymbolAddress((void**)&p_in,  g_in);
    cudaGetSymbolAddress((void**)&p_xh,  g_xh);
    cudaGetSymbolAddress((void**)&p_w0h, g_w0h);
    cudaGetSymbolAddress((void**)&p_w1h, g_w1h);
    cudaGetSymbolAddress((void**)&p_w2h, g_w2h);
    (void)in_sizes; (void)n_in; (void)out_size;

    cudaFuncSetAttribute(gemm_f16_kernel,
                         cudaFuncAttributeMaxDynamicSharedMemorySize, GEMM_SMEM_BYTES);

    const int T = 256;
    const int nodeBlocks = (N_NODES + T - 1) / T;
    const int edgeBlocks = (N_EDGES + T - 1) / T;
    const int warpBlocks = (N_NODES * 32 + T - 1) / T;

    dim3 gemmGrid((N_NODES + GBM - 1) / GBM, HID / GBN);

    // Fork: CSR build on s2, cvt + layer-0 GEMM on default stream (independent)
    cudaStream_t s2;
    cudaStreamCreateWithFlags(&s2, cudaStreamNonBlocking);
    cudaEvent_t evFork, evJoin;
    cudaEventCreateWithFlags(&evFork, cudaEventDisableTiming);
    cudaEventCreateWithFlags(&evJoin, cudaEventDisableTiming);
    // (stream/events intentionally leaked: kernel_launch is called O(1) times,
    //  and destroying them mid-capture would invalidate the captured graph)

    cudaEventRecord(evFork, 0);
    cudaStreamWaitEvent(s2, evFork, 0);

    // s2: CSR build chain
    zero_kernel<<<nodeBlocks, T, 0, s2>>>();
    deg_count_kernel<<<edgeBlocks, T, 0, s2>>>(dst);
    dinv_kernel<<<nodeBlocks, T, 0, s2>>>();
    scan_bsum_kernel<<<NB_SCAN, 256, 0, s2>>>();
    scan_boff_kernel<<<1, 256, 0, s2>>>();
    scan_apply_kernel<<<NB_SCAN, 256, 0, s2>>>();
    scatter_kernel<<<edgeBlocks, T, 0, s2>>>(src, dst);
    cudaEventRecord(evJoin, s2);

    // default stream: fp16 conversion + layer-0 GEMM
    cvt_x_kernel<<<(N_NODES * (IN_CH / 4) + T - 1) / T, T>>>(x);
    cvt_w_kernel<<<(IN_CH * HID + T - 1) / T, T>>>(W0, W1, W2);
    gemm_f16_kernel<<<gemmGrid, T, GEMM_SMEM_BYTES>>>(IN_CH, p_xh, p_w0h, p_h);

    // join: aggregation needs CSR + gemm0
    cudaStreamWaitEvent(0, evJoin, 0);
    agg_relu_kernel<<<warpBlocks, T>>>(p_h, b0, p_in);

    // layer 1
    gemm_f16_kernel<<<gemmGrid, T, GEMM_SMEM_BYTES>>>(HID, p_in, p_w1h, p_h);
    agg_relu_kernel<<<warpBlocks, T>>>(p_h, b1, p_in);

    // layer 2 + fused readout
    gemm_f16_kernel<<<gemmGrid, T, GEMM_SMEM_BYTES>>>(HID, p_in, p_w2h, p_h);
    agg_readout_kernel<<<warpBlocks, T>>>(p_h, b2, Wout, bout, out);
}

// round 12
// speedup vs baseline: 4.2359x; 1.0403x over previous
#include <cuda_runtime.h>
#include <cuda_fp16.h>
#include <cstdint>

#define N_NODES 50000
#define N_EDGES 800000
#define IN_CH   512
#define HID     256

// ---------------- scratch (no allocations allowed) ----------------
#define NB_SCAN ((N_NODES + 255) / 256)   // 196

__device__ int      g_degi  [N_NODES];
__device__ float    g_dinv  [N_NODES];
__device__ int      g_rowptr[N_NODES + 1];
__device__ int      g_fill  [N_NODES];
__device__ int      g_bsum  [NB_SCAN];
__device__ int      g_boff  [NB_SCAN];
__device__ int      g_esrc  [N_EDGES];
__device__ float    g_enorm [N_EDGES];
__device__ __half   g_w0h   [IN_CH * HID];               // fp16 W0^T  [n][k]
__device__ __half   g_w1h   [HID * HID];                 // fp16 W1^T
__device__ __half   g_w2h   [HID * HID];                 // fp16 W2^T
__device__ __half   g_h     [(size_t)N_NODES * HID];     // GEMM output (gather operand)
__device__ __half   g_in    [(size_t)N_NODES * HID];     // fp16 relu(agg+b)

// ---------------- degree / norm / CSR build ----------------
__global__ void zero_kernel() {
    int i = blockIdx.x * blockDim.x + threadIdx.x;
    if (i < N_NODES) { g_degi[i] = 0; g_fill[i] = 0; }
}

__global__ void deg_count_kernel(const int* __restrict__ dst) {
    int e = blockIdx.x * blockDim.x + threadIdx.x;
    if (e < N_EDGES) atomicAdd(&g_degi[__ldg(&dst[e])], 1);
}

__global__ void dinv_kernel() {
    int i = blockIdx.x * blockDim.x + threadIdx.x;
    if (i < N_NODES) g_dinv[i] = rsqrtf((float)(g_degi[i] + 1));  // +1 self-loop
}

__global__ void scan_bsum_kernel() {
    __shared__ int sh[256];
    int t = threadIdx.x;
    int i = blockIdx.x * 256 + t;
    sh[t] = (i < N_NODES) ? g_degi[i] : 0;
    __syncthreads();
    for (int off = 128; off > 0; off >>= 1) {
        if (t < off) sh[t] += sh[t + off];
        __syncthreads();
    }
    if (t == 0) g_bsum[blockIdx.x] = sh[0];
}

__global__ void scan_boff_kernel() {
    __shared__ int sh[256];
    int t = threadIdx.x;
    int v = (t < NB_SCAN) ? g_bsum[t] : 0;
    sh[t] = v;
    __syncthreads();
    for (int off = 1; off < 256; off <<= 1) {
        int u = (t >= off) ? sh[t - off] : 0;
        __syncthreads();
        sh[t] += u;
        __syncthreads();
    }
    if (t < NB_SCAN) g_boff[t] = sh[t] - v;
    if (t == 255) g_rowptr[N_NODES] = sh[255];
}

__global__ void scan_apply_kernel() {
    __shared__ int sh[256];
    int t = threadIdx.x;
    int i = blockIdx.x * 256 + t;
    int v = (i < N_NODES) ? g_degi[i] : 0;
    sh[t] = v;
    __syncthreads();
    for (int off = 1; off < 256; off <<= 1) {
        int u = (t >= off) ? sh[t - off] : 0;
        __syncthreads();
        sh[t] += u;
        __syncthreads();
    }
    if (i < N_NODES) g_rowptr[i] = g_boff[blockIdx.x] + sh[t] - v;
}

__global__ void scatter_kernel(const int* __restrict__ src,
                               const int* __restrict__ dst) {
    int e = blockIdx.x * blockDim.x + threadIdx.x;
    if (e < N_EDGES) {
        int s = __ldg(&src[e]);
        int d = __ldg(&dst[e]);
        int pos = g_rowptr[d] + atomicAdd(&g_fill[d], 1);
        g_esrc[pos]  = s;
        g_enorm[pos] = g_dinv[s] * g_dinv[d];
    }
}

// ---------------- weight transpose + fp16 ----------------
__global__ void cvt_w_kernel(const float* __restrict__ W0,
                             const float* __restrict__ W1,
                             const float* __restrict__ W2) {
    int i = blockIdx.x * blockDim.x + threadIdx.x;
    if (i < IN_CH * HID) {
        int n = i / IN_CH, k = i % IN_CH;
        g_w0h[i] = __float2half(__ldg(&W0[k * HID + n]));
    }
    if (i < HID * HID) {
        int n = i / HID, k = i % HID;
        g_w1h[i] = __float2half(__ldg(&W1[k * HID + n]));
        g_w2h[i] = __float2half(__ldg(&W2[k * HID + n]));
    }
}

// ---------------- fp16 mma m16n8k16 + ldmatrix ----------------
__device__ __forceinline__ void mma_f16(float* c,
                                        uint32_t a0, uint32_t a1, uint32_t a2, uint32_t a3,
                                        uint32_t b0, uint32_t b1) {
    asm volatile(
        "mma.sync.aligned.m16n8k16.row.col.f32.f16.f16.f32 "
        "{%0,%1,%2,%3}, {%4,%5,%6,%7}, {%8,%9}, {%0,%1,%2,%3};"
        : "+f"(c[0]), "+f"(c[1]), "+f"(c[2]), "+f"(c[3])
        : "r"(a0), "r"(a1), "r"(a2), "r"(a3), "r"(b0), "r"(b1));
}

__device__ __forceinline__ void ldsm_x4(uint32_t* r, uint32_t addr) {
    asm volatile("ldmatrix.sync.aligned.m8n8.x4.shared.b16 {%0,%1,%2,%3}, [%4];"
                 : "=r"(r[0]), "=r"(r[1]), "=r"(r[2]), "=r"(r[3]) : "r"(addr));
}

// ---------------- fp16 GEMM, full-N CTA, 3-stage cp.async + ldmatrix ----------------
// C[M=50000, 256] = A[M,K] * Wt[256,K]^T.  CTA: 128 rows x 256 cols, 512 threads.
// AF32 variant stages raw fp32 A and converts to fp16 in smem (layer 0).
#define GBM 128
#define GBK 32
#define TSH 40                                // halves per smem row (80 B), conflict-free
#define A_TILE_B (128 * TSH * 2)              // 10240
#define B_TILE_B (256 * TSH * 2)              // 20480
#define BBASE (3 * A_TILE_B)                  // 30720
#define SCR_BASE (BBASE + 3 * B_TILE_B)       // 92160
#define SCR_STRIDE 144                        // bytes per fp32 scratch row (16B mult)
#define SCR_TILE (128 * SCR_STRIDE)           // 18432
#define GEMM_SMEM_F16 SCR_BASE                // 92160
#define GEMM_SMEM_F32 (SCR_BASE + 3 * SCR_TILE)   // 147456

template <bool AF32>
__global__ __launch_bounds__(512) void gemm_f16_kernel(
    int K,
    const void* __restrict__ Aptr,    // [M, K] fp32 (AF32) or fp16
    const __half* __restrict__ Wt,    // [256, K]
    __half* __restrict__ Ch)          // [M, 256]
{
    extern __shared__ char smc[];
    const uint32_t sbase = (uint32_t)__cvta_generic_to_shared(smc);

    const int tid  = threadIdx.x;
    const int lane = tid & 31;
    const int warp = tid >> 5;
    const int wm   = warp >> 3;          // 0..1
    const int wn   = warp & 7;           // 0..7
    const int g    = lane >> 2;          // 0..7  (epilogue row)
    const int t    = lane & 3;           // 0..3  (epilogue col pair)
    const int lrow = lane & 7;
    const int lgrp = lane >> 3;

    const int crow0 = blockIdx.x * GBM;

    float acc[4][4][4];
#pragma unroll
    for (int fm = 0; fm < 4; fm++)
#pragma unroll
        for (int fn = 0; fn < 4; fn++)
#pragma unroll
            for (int q = 0; q < 4; q++) acc[fm][fn][q] = 0.0f;

    // ldmatrix byte offsets within a tile buffer
    uint32_t aOff[4];
#pragma unroll
    for (int fm = 0; fm < 4; fm++)
        aOff[fm] = (uint32_t)(((wm * 64 + fm * 16 + ((lgrp & 1) << 3) + lrow) * TSH +
                               ((lgrp >> 1) << 3)) * 2);
    uint32_t bOff[2];
#pragma unroll
    for (int p = 0; p < 2; p++)
        bOff[p] = (uint32_t)(((wn * 32 + p * 16 + ((lgrp >> 1) << 3) + lrow) * TSH +
                              ((lgrp & 1) << 3)) * 2);

    auto stage = [&](int buf, int k0) {
        if (AF32) {
            // A fp32 -> scratch: 128 rows x 128B = 1024 x 16B chunks
            const float* A32 = (const float*)Aptr;
#pragma unroll
            for (int i = 0; i < 2; i++) {
                int idx   = tid + i * 512;
                int row   = idx >> 3;
                int chunk = idx & 7;
                int grow  = crow0 + row;
                uint32_t dstp = sbase + (uint32_t)(SCR_BASE + buf * SCR_TILE + row * SCR_STRIDE + chunk * 16);
                const float* srcp = A32 + (size_t)(grow < N_NODES ? grow : 0) * K + k0 + chunk * 4;
                int sz = (grow < N_NODES) ? 16 : 0;
                asm volatile("cp.async.ca.shared.global [%0], [%1], 16, %2;"
                             :: "r"(dstp), "l"(srcp), "r"(sz));
            }
        } else {
            // A fp16: 128 rows x 64B = 512 x 16B chunks
            const __half* A16 = (const __half*)Aptr;
            int row   = tid >> 2;
            int chunk = tid & 3;
            int grow  = crow0 + row;
            uint32_t dstp = sbase + (uint32_t)(buf * A_TILE_B + row * (TSH * 2) + chunk * 16);
            const __half* srcp = A16 + (size_t)(grow < N_NODES ? grow : 0) * K + k0 + chunk * 8;
            int sz = (grow < N_NODES) ? 16 : 0;
            asm volatile("cp.async.ca.shared.global [%0], [%1], 16, %2;"
                         :: "r"(dstp), "l"(srcp), "r"(sz));
        }
        // B: 256 rows x 64B = 1024 x 16B chunks
#pragma unroll
        for (int i = 0; i < 2; i++) {
            int idx   = tid + i * 512;
            int row   = idx >> 2;
            int chunk = idx & 3;
            uint32_t dstp = sbase + (uint32_t)(BBASE + buf * B_TILE_B + row * (TSH * 2) + chunk * 16);
            const __half* srcp = Wt + (size_t)row * K + k0 + chunk * 8;
            asm volatile("cp.async.ca.shared.global [%0], [%1], 16;"
                         :: "r"(dstp), "l"(srcp));
        }
        asm volatile("cp.async.commit_group;");
    };

    const int nk = K / GBK;        // 16 (layer 0) or 8
    stage(0, 0);
    stage(1, GBK);

    for (int ki = 0; ki < nk; ki++) {
        const int buf = ki % 3;
        if (ki + 1 < nk) {
            asm volatile("cp.async.wait_group 1;");
        } else {
            asm volatile("cp.async.wait_group 0;");
        }
        __syncthreads();

        if (AF32) {
            // convert scratch fp32 -> fp16 A tile for this buffer
            int row   = tid >> 2;
            int chunk = tid & 3;          // 8 halves per task
            const float* sp = reinterpret_cast<const float*>(smc + SCR_BASE + buf * SCR_TILE +
                                                             row * SCR_STRIDE) + chunk * 8;
            float4 v0 = *reinterpret_cast<const float4*>(sp);
            float4 v1 = *reinterpret_cast<const float4*>(sp + 4);
            __half2 h0 = __floats2half2_rn(v0.x, v0.y);
            __half2 h1 = __floats2half2_rn(v0.z, v0.w);
            __half2 h2 = __floats2half2_rn(v1.x, v1.y);
            __half2 h3 = __floats2half2_rn(v1.z, v1.w);
            uint4 u;
            u.x = *reinterpret_cast<uint32_t*>(&h0);
            u.y = *reinterpret_cast<uint32_t*>(&h1);
            u.z = *reinterpret_cast<uint32_t*>(&h2);
            u.w = *reinterpret_cast<uint32_t*>(&h3);
            *reinterpret_cast<uint4*>(smc + buf * A_TILE_B + row * (TSH * 2) + chunk * 16) = u;
            __syncthreads();
        }

        if (ki + 2 < nk) stage((ki + 2) % 3, (ki + 2) * GBK);

        const uint32_t aBase = sbase + (uint32_t)(buf * A_TILE_B);
        const uint32_t bBase = sbase + (uint32_t)(BBASE + buf * B_TILE_B);

#pragma unroll
        for (int kc = 0; kc < 2; kc++) {
            const uint32_t kb = kc * 32;     // 16 halves = 32 bytes
            uint32_t a[4][4];
            uint32_t b[2][4];
#pragma unroll
            for (int fm = 0; fm < 4; fm++) ldsm_x4(a[fm], aBase + aOff[fm] + kb);
#pragma unroll
            for (int p = 0; p < 2; p++)    ldsm_x4(b[p], bBase + bOff[p] + kb);
#pragma unroll
            for (int fm = 0; fm < 4; fm++)
#pragma unroll
                for (int fn = 0; fn < 4; fn++)
                    mma_f16(acc[fm][fn],
                            a[fm][0], a[fm][1], a[fm][2], a[fm][3],
                            b[fn >> 1][(fn & 1) * 2], b[fn >> 1][(fn & 1) * 2 + 1]);
        }
    }
    __syncthreads();

    // Epilogue: fp16 stores (half2, c even)
#pragma unroll
    for (int fm = 0; fm < 4; fm++) {
        int r0 = crow0 + wm * 64 + fm * 16 + g;
        int r1 = r0 + 8;
#pragma unroll
        for (int fn = 0; fn < 4; fn++) {
            int c = wn * 32 + fn * 8 + 2 * t;
            if (r0 < N_NODES)
                *reinterpret_cast<__half2*>(Ch + (size_t)r0 * HID + c) =
                    __floats2half2_rn(acc[fm][fn][0], acc[fm][fn][1]);
            if (r1 < N_NODES)
                *reinterpret_cast<__half2*>(Ch + (size_t)r1 * HID + c) =
                    __floats2half2_rn(acc[fm][fn][2], acc[fm][fn][3]);
        }
    }
}

// ---------------- CSR aggregation (fp16 gather), fused epilogues ----------------
__device__ __forceinline__ void agg_node(int node, const __half* __restrict__ h,
                                         int lane, float acc[8]) {
#pragma unroll
    for (int q = 0; q < 8; q++) acc[q] = 0.0f;

    int p0 = g_rowptr[node];
    int p1 = g_rowptr[node + 1];
    for (int base = p0; base < p1; base += 32) {
        int nn = min(32, p1 - base);
        int   sv = 0; float nv = 0.f;
        if (base + lane < p1) {
            sv = __ldg(&g_esrc[base + lane]);
            nv = __ldg(&g_enorm[base + lane]);
        }
        for (int j = 0; j < nn; j++) {
            int   s   = __shfl_sync(0xffffffffu, sv, j);
            float nrm = __shfl_sync(0xffffffffu, nv, j);
            uint4 raw = __ldg(reinterpret_cast<const uint4*>(h + (size_t)s * HID) + lane);
            const __half2* hv = reinterpret_cast<const __half2*>(&raw);
#pragma unroll
            for (int q = 0; q < 4; q++) {
                float2 f = __half22float2(hv[q]);
                acc[2 * q + 0] = fmaf(nrm, f.x, acc[2 * q + 0]);
                acc[2 * q + 1] = fmaf(nrm, f.y, acc[2 * q + 1]);
            }
        }
    }
    // self-loop
    float d = g_dinv[node];
    float w = d * d;
    uint4 raw = __ldg(reinterpret_cast<const uint4*>(h + (size_t)node * HID) + lane);
    const __half2* hv = reinterpret_cast<const __half2*>(&raw);
#pragma unroll
    for (int q = 0; q < 4; q++) {
        float2 f = __half22float2(hv[q]);
        acc[2 * q + 0] = fmaf(w, f.x, acc[2 * q + 0]);
        acc[2 * q + 1] = fmaf(w, f.y, acc[2 * q + 1]);
    }
}

__global__ void agg_relu_kernel(const __half* __restrict__ h,
                                const float* __restrict__ b,
                                __half* __restrict__ outbuf) {
    int gtid = blockIdx.x * blockDim.x + threadIdx.x;
    int node = gtid >> 5;
    int lane = threadIdx.x & 31;
    if (node >= N_NODES) return;

    float acc[8];
    agg_node(node, h, lane, acc);

    const float4* bp = reinterpret_cast<const float4*>(b);
    float4 b0 = __ldg(&bp[2 * lane]);
    float4 b1 = __ldg(&bp[2 * lane + 1]);

    __half2 h0 = __floats2half2_rn(fmaxf(acc[0] + b0.x, 0.f), fmaxf(acc[1] + b0.y, 0.f));
    __half2 h1 = __floats2half2_rn(fmaxf(acc[2] + b0.z, 0.f), fmaxf(acc[3] + b0.w, 0.f));
    __half2 h2 = __floats2half2_rn(fmaxf(acc[4] + b1.x, 0.f), fmaxf(acc[5] + b1.y, 0.f));
    __half2 h3 = __floats2half2_rn(fmaxf(acc[6] + b1.z, 0.f), fmaxf(acc[7] + b1.w, 0.f));

    uint4 u;
    u.x = *reinterpret_cast<uint32_t*>(&h0);
    u.y = *reinterpret_cast<uint32_t*>(&h1);
    u.z = *reinterpret_cast<uint32_t*>(&h2);
    u.w = *reinterpret_cast<uint32_t*>(&h3);
    reinterpret_cast<uint4*>(outbuf + (size_t)node * HID)[lane] = u;
}

__global__ void agg_readout_kernel(const __half* __restrict__ h,
                                   const float* __restrict__ b,
                                   const float* __restrict__ Wout,
                                   const float* __restrict__ bout,
                                   float* __restrict__ out) {
    int gtid = blockIdx.x * blockDim.x + threadIdx.x;
    int node = gtid >> 5;
    int lane = threadIdx.x & 31;
    if (node >= N_NODES) return;

    float acc[8];
    agg_node(node, h, lane, acc);

    const float4* bp = reinterpret_cast<const float4*>(b);
    const float4* wp = reinterpret_cast<const float4*>(Wout);
    float4 b0 = __ldg(&bp[2 * lane]);
    float4 b1 = __ldg(&bp[2 * lane + 1]);
    float4 w0 = __ldg(&wp[2 * lane]);
    float4 w1 = __ldg(&wp[2 * lane + 1]);

    float s = fmaxf(acc[0] + b0.x, 0.f) * w0.x + fmaxf(acc[1] + b0.y, 0.f) * w0.y +
              fmaxf(acc[2] + b0.z, 0.f) * w0.z + fmaxf(acc[3] + b0.w, 0.f) * w0.w +
              fmaxf(acc[4] + b1.x, 0.f) * w1.x + fmaxf(acc[5] + b1.y, 0.f) * w1.y +
              fmaxf(acc[6] + b1.z, 0.f) * w1.z + fmaxf(acc[7] + b1.w, 0.f) * w1.w;
#pragma unroll
    for (int o = 16; o > 0; o >>= 1) s += __shfl_down_sync(0xffffffffu, s, o);
    if (lane == 0) out[node] = s + __ldg(&bout[0]);
}

// ---------------- host launcher ----------------
extern "C" void kernel_launch(void* const* d_in, const int* in_sizes, int n_in,
                              void* d_out, int out_size) {
    const float* x    = (const float*)d_in[0];
    const int*   ei   = (const int*)d_in[1];   // delivered as int32
    const float* W0   = (const float*)d_in[2];
    const float* b0   = (const float*)d_in[3];
    const float* W1   = (const float*)d_in[4];
    const float* b1   = (const float*)d_in[5];
    const float* W2   = (const float*)d_in[6];
    const float* b2   = (const float*)d_in[7];
    const float* Wout = (const float*)d_in[8];
    const float* bout = (const float*)d_in[9];
    float*       out  = (float*)d_out;

    const int* src = ei;             // edge_index[0]
    const int* dst = ei + N_EDGES;   // edge_index[1]

    __half *p_h, *p_in, *p_w0h, *p_w1h, *p_w2h;
    cudaGetSymbolAddress((void**)&p_h,   g_h);
    cudaGetSymbolAddress((void**)&p_in,  g_in);
    cudaGetSymbolAddress((void**)&p_w0h, g_w0h);
    cudaGetSymbolAddress((void**)&p_w1h, g_w1h);
    cudaGetSymbolAddress((void**)&p_w2h, g_w2h);
    (void)in_sizes; (void)n_in; (void)out_size;

    cudaFuncSetAttribute(gemm_f16_kernel<true>,
                         cudaFuncAttributeMaxDynamicSharedMemorySize, GEMM_SMEM_F32);
    cudaFuncSetAttribute(gemm_f16_kernel<false>,
                         cudaFuncAttributeMaxDynamicSharedMemorySize, GEMM_SMEM_F16);

    const int T = 256;
    const int nodeBlocks = (N_NODES + T - 1) / T;
    const int edgeBlocks = (N_EDGES + T - 1) / T;
    const int warpBlocks = (N_NODES * 32 + T - 1) / T;
    const int gemmGrid   = (N_NODES + GBM - 1) / GBM;   // 391

    // Fork: CSR build on s2, cvt_w + layer-0 GEMM on default stream (independent)
    cudaStream_t s2;
    cudaStreamCreateWithFlags(&s2, cudaStreamNonBlocking);
    cudaEvent_t evFork, evJoin;
    cudaEventCreateWithFlags(&evFork, cudaEventDisableTiming);
    cudaEventCreateWithFlags(&evJoin, cudaEventDisableTiming);
    // (stream/events intentionally leaked: kernel_launch is called O(1) times)

    cudaEventRecord(evFork, 0);
    cudaStreamWaitEvent(s2, evFork, 0);

    // s2: CSR build chain
    zero_kernel<<<nodeBlocks, T, 0, s2>>>();
    deg_count_kernel<<<edgeBlocks, T, 0, s2>>>(dst);
    dinv_kernel<<<nodeBlocks, T, 0, s2>>>();
    scan_bsum_kernel<<<NB_SCAN, 256, 0, s2>>>();
    scan_boff_kernel<<<1, 256, 0, s2>>>();
    scan_apply_kernel<<<NB_SCAN, 256, 0, s2>>>();
    scatter_kernel<<<edgeBlocks, T, 0, s2>>>(src, dst);
    cudaEventRecord(evJoin, s2);

    // default stream: weight conversion + layer-0 GEMM (reads fp32 x directly)
    cvt_w_kernel<<<(IN_CH * HID + T - 1) / T, T>>>(W0, W1, W2);
    gemm_f16_kernel<true><<<gemmGrid, 512, GEMM_SMEM_F32>>>(IN_CH, x, p_w0h, p_h);

    // join: aggregation needs CSR + gemm0
    cudaStreamWaitEvent(0, evJoin, 0);
    agg_relu_kernel<<<warpBlocks, T>>>(p_h, b0, p_in);

    // layer 1
    gemm_f16_kernel<false><<<gemmGrid, 512, GEMM_SMEM_F16>>>(HID, p_in, p_w1h, p_h);
    agg_relu_kernel<<<warpBlocks, T>>>(p_h, b1, p_in);

    // layer 2 + fused readout
    gemm_f16_kernel<false><<<gemmGrid, 512, GEMM_SMEM_F16>>>(HID, p_in, p_w2h, p_h);
    agg_readout_kernel<<<warpBlocks, T>>>(p_h, b2, Wout, bout, out);
}